// round 13
// baseline (speedup 1.0000x reference)
#include <cuda_runtime.h>
#include <cuda_bf16.h>
#include <cstdint>

#define SEQ    2048
#define BATCH  4
#define DMODEL 1024
#define DINT   64
#define MTOT   (SEQ * BATCH)   // 8192
#define KP2    (2 * SEQ)       // 4096: [hi|lo] rows for aten operands
#define KPV2   (2 * DMODEL)    // 2048: [hi|lo] rows for projv operands

// ---- scratch (device globals: allocation-free) ----
__device__ float g_q[BATCH * SEQ * DINT];
__device__ float g_k[BATCH * SEQ * DINT];
__device__ float g_v[BATCH * SEQ * DMODEL];
__device__ float g_colsum[BATCH * SEQ];
__device__ alignas(256) __nv_bfloat16 g_a2[(size_t)BATCH * SEQ * KP2];     // probs  [b][q][hi|lo]
__device__ alignas(256) __nv_bfloat16 g_b2[(size_t)BATCH * DMODEL * KP2];  // v^T    [b][n][hi|lo]
__device__ alignas(256) __nv_bfloat16 g_xv2[(size_t)MTOT * KPV2];          // value  [m][hi|lo]
__device__ alignas(256) __nv_bfloat16 g_wv2[(size_t)DMODEL * KPV2];        // Wv^T   [n][hi|lo]

// ================= baseline-ISA helpers =================
__device__ __forceinline__ uint32_t smem_u32(const void* p) {
    uint32_t a;
    asm("{ .reg .u64 t; cvta.to.shared.u64 t, %1; cvt.u32.u64 %0, t; }" : "=r"(a) : "l"(p));
    return a;
}
#define SMEM_SWIZZLE_128B(o) ((o) ^ (((o) >> 3) & 0x70))
#define CP_ASYNC16(dst, src) \
    asm volatile("cp.async.cg.shared.global [%0], [%1], 16;" :: "r"(dst), "l"(src) : "memory")
#define CP_COMMIT() asm volatile("cp.async.commit_group;" ::: "memory")
#define CP_WAIT(n)  asm volatile("cp.async.wait_group %0;" :: "n"(n) : "memory")
#define LDSM_X4(r0, r1, r2, r3, addr) \
    asm volatile("ldmatrix.sync.aligned.m8n8.x4.shared.b16 {%0,%1,%2,%3}, [%4];" \
        : "=r"(r0), "=r"(r1), "=r"(r2), "=r"(r3) : "r"(addr))
#define MMA16816(d, a0, a1, a2, a3, b0, b1) \
    asm volatile("mma.sync.aligned.m16n8k16.row.col.f32.bf16.bf16.f32 " \
        "{%0,%1,%2,%3}, {%4,%5,%6,%7}, {%8,%9}, {%0,%1,%2,%3};" \
        : "+f"((d)[0]), "+f"((d)[1]), "+f"((d)[2]), "+f"((d)[3]) \
        : "r"(a0), "r"(a1), "r"(a2), "r"(a3), "r"(b0), "r"(b1))

__device__ __forceinline__ void split2(float v, __nv_bfloat16& h, __nv_bfloat16& l) {
    h = __float2bfloat16(v);
    l = __float2bfloat16(v - __bfloat162float(h));
}

// ============================================================
// q+k projections fused: X(8192,1024) @ W(1024,64) + bias
// ============================================================
__global__ void projqk_kernel(const float* __restrict__ Q,
                              const float* __restrict__ Wq,
                              const float* __restrict__ bq,
                              const float* __restrict__ Kin,
                              const float* __restrict__ Wk,
                              const float* __restrict__ bk)
{
    __shared__ float As[16][64];
    __shared__ float Bs[16][64];
    const int tid = threadIdx.x;
    const int tx = tid & 15, ty = tid >> 4;
    const int m0 = blockIdx.x * 64;
    const int which = blockIdx.y;
    const float* X    = which ? Kin : Q;
    const float* W    = which ? Wk  : Wq;
    const float* bias = which ? bk  : bq;
    float* out = which ? g_k : g_q;

    float acc[4][4] = {};

    for (int k0 = 0; k0 < DMODEL; k0 += 16) {
        {
            int row = tid >> 2;
            int kg  = (tid & 3) * 4;
            float4 v = *reinterpret_cast<const float4*>(&X[(size_t)(m0 + row) * DMODEL + k0 + kg]);
            As[kg + 0][row] = v.x; As[kg + 1][row] = v.y;
            As[kg + 2][row] = v.z; As[kg + 3][row] = v.w;
        }
        {
            int row = tid >> 4;
            int col = (tid & 15) * 4;
            *reinterpret_cast<float4*>(&Bs[row][col]) =
                *reinterpret_cast<const float4*>(&W[(size_t)(k0 + row) * DINT + col]);
        }
        __syncthreads();
#pragma unroll
        for (int kk = 0; kk < 16; kk++) {
            float a[4], b[4];
#pragma unroll
            for (int i = 0; i < 4; i++) a[i] = As[kk][ty * 4 + i];
#pragma unroll
            for (int j = 0; j < 4; j++) b[j] = Bs[kk][tx * 4 + j];
#pragma unroll
            for (int i = 0; i < 4; i++)
#pragma unroll
                for (int j = 0; j < 4; j++) acc[i][j] += a[i] * b[j];
        }
        __syncthreads();
    }

#pragma unroll
    for (int i = 0; i < 4; i++) {
        int m = m0 + ty * 4 + i;
        int s = m >> 2, b = m & 3;
        float* orow = &out[(size_t)(b * SEQ + s) * DINT];
#pragma unroll
        for (int j = 0; j < 4; j++) {
            int n = tx * 4 + j;
            orow[n] = acc[i][j] + bias[n];
        }
    }
}

// ============================================================
// value split: value[m][k] -> g_xv2[m][ hi | lo ]
// ============================================================
__global__ void xvsplit_kernel(const float* __restrict__ X)
{
    size_t i4 = ((size_t)blockIdx.x * 256 + threadIdx.x) * 4;
    int k = (int)(i4 & (DMODEL - 1));
    int m = (int)(i4 >> 10);
    float4 p = *reinterpret_cast<const float4*>(&X[i4]);
    __nv_bfloat16 h0, h1, h2, h3, l0, l1, l2, l3;
    split2(p.x, h0, l0); split2(p.y, h1, l1);
    split2(p.z, h2, l2); split2(p.w, h3, l3);
    __nv_bfloat16* row = g_xv2 + (size_t)m * KPV2;
    __nv_bfloat162 ha; ha.x = h0; ha.y = h1;
    __nv_bfloat162 hb; hb.x = h2; hb.y = h3;
    __nv_bfloat162 la; la.x = l0; la.y = l1;
    __nv_bfloat162 lb; lb.x = l2; lb.y = l3;
    *reinterpret_cast<__nv_bfloat162*>(row + k)              = ha;
    *reinterpret_cast<__nv_bfloat162*>(row + k + 2)          = hb;
    *reinterpret_cast<__nv_bfloat162*>(row + DMODEL + k)     = la;
    *reinterpret_cast<__nv_bfloat162*>(row + DMODEL + k + 2) = lb;
}

// ============================================================
// Wv split+transpose: W[k][n] -> g_wv2[n][ hi | lo ]
// ============================================================
__global__ void wvsplit_kernel(const float* __restrict__ W)
{
    __shared__ float t[32][33];
    const int tid = threadIdx.x;
    const int n0 = blockIdx.x * 32;
    const int k0 = blockIdx.y * 32;

#pragma unroll
    for (int r = 0; r < 4; r++) {
        int idx = tid + r * 256;
        int kl = idx >> 5, nl = idx & 31;
        t[kl][nl] = W[(size_t)(k0 + kl) * DMODEL + n0 + nl];
    }
    __syncthreads();

#pragma unroll
    for (int r = 0; r < 2; r++) {
        int idx = tid + r * 256;
        int nl = idx >> 4;
        int kp = (idx & 15) * 2;
        float v0 = t[kp][nl], v1 = t[kp + 1][nl];
        __nv_bfloat16 h0, h1, l0, l1;
        split2(v0, h0, l0); split2(v1, h1, l1);
        __nv_bfloat16* row = g_wv2 + (size_t)(n0 + nl) * KPV2;
        __nv_bfloat162 hh; hh.x = h0; hh.y = h1;
        __nv_bfloat162 ll; ll.x = l0; ll.y = l1;
        *reinterpret_cast<__nv_bfloat162*>(row + k0 + kp)          = hh;
        *reinterpret_cast<__nv_bfloat162*>(row + DMODEL + k0 + kp) = ll;
    }
}

// ============================================================
// shared GEMM core (double-buffered, 512 threads / 16 warps):
// D[128,128] = sum over chunks of Ahi*Bhi + Alo*Bhi + Ahi*Blo
// warp grid 4x4, warp tile 32x32. 2 buffers x 4 tiles x 16KB.
// ============================================================
#define T_A_HI 0
#define T_A_LO 16384
#define T_B_HI 32768
#define T_B_LO 49152
#define GM_BUF  65536
#define GM_SMEM 131072

struct GemmAcc { float a[2][4][4]; };

__device__ __forceinline__ void gemm_load_group(
    uint32_t sbase, int buf,
    const __nv_bfloat16* Ag, const __nv_bfloat16* Bg,
    int k0, int kseg, int rowlen, int tid)
{
    const uint32_t base = sbase + buf * GM_BUF;
#pragma unroll
    for (int r = 0; r < 2; r++) {
        int idx = tid + r * 512;
        int row = idx >> 3, u = idx & 7;
        uint32_t off = SMEM_SWIZZLE_128B((uint32_t)(row * 128 + u * 16));
        const __nv_bfloat16* arow = Ag + (size_t)row * rowlen + k0 + u * 8;
        const __nv_bfloat16* brow = Bg + (size_t)row * rowlen + k0 + u * 8;
        CP_ASYNC16(base + T_A_HI + off, arow);
        CP_ASYNC16(base + T_A_LO + off, arow + kseg);
        CP_ASYNC16(base + T_B_HI + off, brow);
        CP_ASYNC16(base + T_B_LO + off, brow + kseg);
    }
}

__device__ __forceinline__ void gemm_split_mainloop(
    GemmAcc& g, uint32_t sbase,
    const __nv_bfloat16* Ag, const __nv_bfloat16* Bg,
    int kseg, int rowlen, int nchunk, int tid, int wm, int wn, int lane)
{
    gemm_load_group(sbase, 0, Ag, Bg, 0, kseg, rowlen, tid);
    CP_COMMIT();

#pragma unroll 1
    for (int c = 0; c < nchunk; c++) {
        const int buf = c & 1;
        if (c + 1 < nchunk) {
            gemm_load_group(sbase, buf ^ 1, Ag, Bg, (c + 1) * 64, kseg, rowlen, tid);
            CP_COMMIT();
            CP_WAIT(1);
        } else {
            CP_WAIT(0);
        }
        __syncthreads();

        const uint32_t base = sbase + buf * GM_BUF;

#pragma unroll
        for (int kk = 0; kk < 4; kk++) {
            // A fragments: 2 m16 tiles (32 rows), hi and lo
            uint32_t af_h[8], af_l[8];
#pragma unroll
            for (int i = 0; i < 2; i++) {
                int row = wm * 32 + i * 16 + (lane & 15);
                uint32_t off = SMEM_SWIZZLE_128B(
                    (uint32_t)(row * 128 + kk * 32 + ((lane >> 4) & 1) * 16));
                LDSM_X4(af_h[i * 4 + 0], af_h[i * 4 + 1], af_h[i * 4 + 2], af_h[i * 4 + 3],
                        base + T_A_HI + off);
                LDSM_X4(af_l[i * 4 + 0], af_l[i * 4 + 1], af_l[i * 4 + 2], af_l[i * 4 + 3],
                        base + T_A_LO + off);
            }
            // pass 0: B_hi vs A_hi + A_lo; pass 1: B_lo vs A_hi
#pragma unroll
            for (int pass = 0; pass < 2; pass++) {
                uint32_t bf[8];
                uint32_t tbase = base + (pass ? T_B_LO : T_B_HI);
#pragma unroll
                for (int j = 0; j < 2; j++) {
                    int row = wn * 32 + j * 16 + ((lane >> 1) & 8) + (lane & 7);
                    uint32_t off = SMEM_SWIZZLE_128B(
                        (uint32_t)(row * 128 + kk * 32 + ((lane >> 3) & 1) * 16));
                    LDSM_X4(bf[j * 4 + 0], bf[j * 4 + 1], bf[j * 4 + 2], bf[j * 4 + 3],
                            tbase + off);
                }
#pragma unroll
                for (int i = 0; i < 2; i++)
#pragma unroll
                    for (int j = 0; j < 4; j++) {
                        int bidx = (j >> 1) * 4 + (j & 1) * 2;
                        MMA16816(g.a[i][j],
                                 af_h[i * 4 + 0], af_h[i * 4 + 1], af_h[i * 4 + 2], af_h[i * 4 + 3],
                                 bf[bidx], bf[bidx + 1]);
                        if (pass == 0)
                            MMA16816(g.a[i][j],
                                     af_l[i * 4 + 0], af_l[i * 4 + 1], af_l[i * 4 + 2], af_l[i * 4 + 3],
                                     bf[bidx], bf[bidx + 1]);
                    }
            }
        }
        __syncthreads();
    }
}

// ============================================================
// projv: g_v = value @ Wv + bv   (M=8192, N=1024, K=1024 split)
// ============================================================
__global__ void __launch_bounds__(512, 1) projv_mma_kernel(const float* __restrict__ bias)
{
    extern __shared__ char smem[];
    const int tid = threadIdx.x;
    const int wid = tid >> 5, lane = tid & 31;
    const int wm = wid & 3, wn = wid >> 2;
    const int m0 = blockIdx.y * 128;
    const int n0 = blockIdx.x * 128;
    const uint32_t sbase = smem_u32(smem);

    GemmAcc g = {};
    gemm_split_mainloop(g, sbase,
                        g_xv2 + (size_t)m0 * KPV2,
                        g_wv2 + (size_t)n0 * KPV2,
                        DMODEL, KPV2, DMODEL / 64, tid, wm, wn, lane);

#pragma unroll
    for (int i = 0; i < 2; i++) {
        int m_a = m0 + wm * 32 + i * 16 + (lane >> 2);
        int m_b = m_a + 8;
        int sa = m_a >> 2, ba = m_a & 3;
        int sb = m_b >> 2, bb2 = m_b & 3;
#pragma unroll
        for (int j = 0; j < 4; j++) {
            int n = n0 + wn * 32 + j * 8 + (lane & 3) * 2;
            float2 bias2 = *reinterpret_cast<const float2*>(bias + n);
            float2 lo = make_float2(g.a[i][j][0] + bias2.x, g.a[i][j][1] + bias2.y);
            float2 hi = make_float2(g.a[i][j][2] + bias2.x, g.a[i][j][3] + bias2.y);
            *reinterpret_cast<float2*>(g_v + ((size_t)(ba * SEQ + sa)) * DMODEL + n)  = lo;
            *reinterpret_cast<float2*>(g_v + ((size_t)(bb2 * SEQ + sb)) * DMODEL + n) = hi;
        }
    }
}

// ============================================================
// v split+transpose: g_v[b][s][n] -> g_b2[b][n][ hi | lo ]
// ============================================================
__global__ void vsplit_kernel()
{
    __shared__ float t[32][33];
    const int tid = threadIdx.x;
    const int b  = blockIdx.z;
    const int n0 = blockIdx.x * 32;
    const int s0 = blockIdx.y * 32;

#pragma unroll
    for (int r = 0; r < 4; r++) {
        int idx = tid + r * 256;
        int sl = idx >> 5, nl = idx & 31;
        t[sl][nl] = g_v[((size_t)(b * SEQ + s0 + sl)) * DMODEL + n0 + nl];
    }
    __syncthreads();

#pragma unroll
    for (int r = 0; r < 2; r++) {
        int idx = tid + r * 256;
        int nl = idx >> 4;
        int sp = (idx & 15) * 2;
        float v0 = t[sp][nl], v1 = t[sp + 1][nl];
        __nv_bfloat16 h0, h1, l0, l1;
        split2(v0, h0, l0); split2(v1, h1, l1);
        __nv_bfloat16* row = g_b2 + ((size_t)(b * DMODEL + n0 + nl)) * KP2;
        __nv_bfloat162 hh; hh.x = h0; hh.y = h1;
        __nv_bfloat162 ll; ll.x = l0; ll.y = l1;
        *reinterpret_cast<__nv_bfloat162*>(row + s0 + sp)       = hh;
        *reinterpret_cast<__nv_bfloat162*>(row + SEQ + s0 + sp) = ll;
    }
}

// ============================================================
// scores = q @ k^T * 0.125
// ============================================================
__global__ void scores_kernel(float* __restrict__ probs)
{
    __shared__ float As[32][128];
    __shared__ float Bs[32][128];
    const int tid = threadIdx.x;
    const int tx = tid & 15, ty = tid >> 4;
    const int b  = blockIdx.z;
    const int m0 = blockIdx.y * 128;
    const int n0 = blockIdx.x * 128;

    const float* Q = g_q + (size_t)b * SEQ * DINT;
    const float* K = g_k + (size_t)b * SEQ * DINT;

    float acc[8][8] = {};

    for (int k0 = 0; k0 < DINT; k0 += 32) {
#pragma unroll
        for (int r = 0; r < 4; r++) {
            int idx = tid + r * 256;
            int row = idx >> 3;
            int c4  = (idx & 7) * 4;
            float4 v = *reinterpret_cast<const float4*>(&Q[(size_t)(m0 + row) * DINT + k0 + c4]);
            As[c4 + 0][row] = v.x; As[c4 + 1][row] = v.y;
            As[c4 + 2][row] = v.z; As[c4 + 3][row] = v.w;
        }
#pragma unroll
        for (int r = 0; r < 4; r++) {
            int idx = tid + r * 256;
            int row = idx >> 3;
            int c4  = (idx & 7) * 4;
            float4 v = *reinterpret_cast<const float4*>(&K[(size_t)(n0 + row) * DINT + k0 + c4]);
            Bs[c4 + 0][row] = v.x; Bs[c4 + 1][row] = v.y;
            Bs[c4 + 2][row] = v.z; Bs[c4 + 3][row] = v.w;
        }
        __syncthreads();
#pragma unroll
        for (int kk = 0; kk < 32; kk++) {
            float a[8], bb[8];
            *reinterpret_cast<float4*>(&a[0])  = *reinterpret_cast<float4*>(&As[kk][ty * 8]);
            *reinterpret_cast<float4*>(&a[4])  = *reinterpret_cast<float4*>(&As[kk][ty * 8 + 4]);
            *reinterpret_cast<float4*>(&bb[0]) = *reinterpret_cast<float4*>(&Bs[kk][tx * 8]);
            *reinterpret_cast<float4*>(&bb[4]) = *reinterpret_cast<float4*>(&Bs[kk][tx * 8 + 4]);
#pragma unroll
            for (int i = 0; i < 8; i++)
#pragma unroll
                for (int j = 0; j < 8; j++) acc[i][j] += a[i] * bb[j];
        }
        __syncthreads();
    }

    float* C = probs + (size_t)b * SEQ * SEQ;
#pragma unroll
    for (int i = 0; i < 8; i++) {
        int row = m0 + ty * 8 + i;
        float* orow = &C[(size_t)row * SEQ + n0 + tx * 8];
        float4 v0 = make_float4(acc[i][0] * 0.125f, acc[i][1] * 0.125f,
                                acc[i][2] * 0.125f, acc[i][3] * 0.125f);
        float4 v1 = make_float4(acc[i][4] * 0.125f, acc[i][5] * 0.125f,
                                acc[i][6] * 0.125f, acc[i][7] * 0.125f);
        *reinterpret_cast<float4*>(&orow[0]) = v0;
        *reinterpret_cast<float4*>(&orow[4]) = v1;
    }
}

// ============================================================
// row softmax in place
// ============================================================
__global__ void rowsoftmax_kernel(float* __restrict__ probs)
{
    const int tid = threadIdx.x;
    float* p = probs + (size_t)blockIdx.x * SEQ;

    __shared__ float red[8];

    float4 v0 = reinterpret_cast<float4*>(p)[tid];
    float4 v1 = reinterpret_cast<float4*>(p)[tid + 256];

    float mx = fmaxf(fmaxf(fmaxf(v0.x, v0.y), fmaxf(v0.z, v0.w)),
                     fmaxf(fmaxf(v1.x, v1.y), fmaxf(v1.z, v1.w)));
#pragma unroll
    for (int o = 16; o > 0; o >>= 1)
        mx = fmaxf(mx, __shfl_xor_sync(0xffffffffu, mx, o));
    if ((tid & 31) == 0) red[tid >> 5] = mx;
    __syncthreads();
    {
        float m = red[tid & 7];
#pragma unroll
        for (int o = 4; o > 0; o >>= 1)
            m = fmaxf(m, __shfl_xor_sync(0xffffffffu, m, o));
        mx = m;
    }

    v0.x = __expf(v0.x - mx); v0.y = __expf(v0.y - mx);
    v0.z = __expf(v0.z - mx); v0.w = __expf(v0.w - mx);
    v1.x = __expf(v1.x - mx); v1.y = __expf(v1.y - mx);
    v1.z = __expf(v1.z - mx); v1.w = __expf(v1.w - mx);

    float sum = v0.x + v0.y + v0.z + v0.w + v1.x + v1.y + v1.z + v1.w;
#pragma unroll
    for (int o = 16; o > 0; o >>= 1)
        sum += __shfl_xor_sync(0xffffffffu, sum, o);
    __syncthreads();
    if ((tid & 31) == 0) red[tid >> 5] = sum;
    __syncthreads();
    {
        float s = red[tid & 7];
#pragma unroll
        for (int o = 4; o > 0; o >>= 1)
            s += __shfl_xor_sync(0xffffffffu, s, o);
        sum = s;
    }
    float inv = 1.0f / sum;

    v0.x *= inv; v0.y *= inv; v0.z *= inv; v0.w *= inv;
    v1.x *= inv; v1.y *= inv; v1.z *= inv; v1.w *= inv;
    reinterpret_cast<float4*>(p)[tid]       = v0;
    reinterpret_cast<float4*>(p)[tid + 256] = v1;
}

// ============================================================
// column sums over q
// ============================================================
__global__ void colsum_kernel(const float* __restrict__ probs)
{
    const int k = blockIdx.x * 256 + threadIdx.x;
    const int b = blockIdx.y;
    const float* p = probs + (size_t)b * SEQ * SEQ + k;
    float s = 0.f;
    for (int q = 0; q < SEQ; q++) s += p[(size_t)q * SEQ];
    g_colsum[b * SEQ + k] = s;
}

// ============================================================
// renorm in place + emit bf16 split A2 = [hi | lo]
// ============================================================
__global__ void renorm_split_kernel(float* __restrict__ probs)
{
    size_t i4 = ((size_t)blockIdx.x * 256 + threadIdx.x) * 4;
    int k = (int)(i4 & (SEQ - 1));
    int q = (int)((i4 >> 11) & (SEQ - 1));
    int b = (int)(i4 >> 22);
    float4 p = *reinterpret_cast<float4*>(&probs[i4]);
    const float4 c = *reinterpret_cast<const float4*>(&g_colsum[b * SEQ + k]);
    p.x /= (1e-9f + c.x);
    p.y /= (1e-9f + c.y);
    p.z /= (1e-9f + c.z);
    p.w /= (1e-9f + c.w);
    *reinterpret_cast<float4*>(&probs[i4]) = p;

    __nv_bfloat16 h0, h1, h2, h3, l0, l1, l2, l3;
    split2(p.x, h0, l0); split2(p.y, h1, l1);
    split2(p.z, h2, l2); split2(p.w, h3, l3);

    __nv_bfloat16* row = g_a2 + ((size_t)(b * SEQ + q)) * KP2;
    __nv_bfloat162 ha; ha.x = h0; ha.y = h1;
    __nv_bfloat162 hb; hb.x = h2; hb.y = h3;
    __nv_bfloat162 la; la.x = l0; la.y = l1;
    __nv_bfloat162 lb; lb.x = l2; lb.y = l3;
    *reinterpret_cast<__nv_bfloat162*>(row + k)           = ha;
    *reinterpret_cast<__nv_bfloat162*>(row + k + 2)       = hb;
    *reinterpret_cast<__nv_bfloat162*>(row + SEQ + k)     = la;
    *reinterpret_cast<__nv_bfloat162*>(row + SEQ + k + 2) = lb;
}

// ============================================================
// aten: out = probs @ v   (per batch 2048x1024, K=2048 split)
// ============================================================
__global__ void __launch_bounds__(512, 1) aten_mma_kernel(float* __restrict__ out)
{
    extern __shared__ char smem[];
    const int tid = threadIdx.x;
    const int wid = tid >> 5, lane = tid & 31;
    const int wm = wid & 3, wn = wid >> 2;
    const int b  = blockIdx.z;
    const int m0 = blockIdx.y * 128;
    const int n0 = blockIdx.x * 128;
    const uint32_t sbase = smem_u32(smem);

    GemmAcc g = {};
    gemm_split_mainloop(g, sbase,
                        g_a2 + (size_t)b * SEQ * KP2 + (size_t)m0 * KP2,
                        g_b2 + (size_t)b * DMODEL * KP2 + (size_t)n0 * KP2,
                        SEQ, KP2, SEQ / 64, tid, wm, wn, lane);

#pragma unroll
    for (int i = 0; i < 2; i++) {
        int q = m0 + wm * 32 + i * 16 + (lane >> 2);
#pragma unroll
        for (int j = 0; j < 4; j++) {
            int n = n0 + wn * 32 + j * 8 + (lane & 3) * 2;
            float2 lo = make_float2(g.a[i][j][0], g.a[i][j][1]);
            float2 hi = make_float2(g.a[i][j][2], g.a[i][j][3]);
            *reinterpret_cast<float2*>(out + ((size_t)q * BATCH + b) * DMODEL + n)       = lo;
            *reinterpret_cast<float2*>(out + ((size_t)(q + 8) * BATCH + b) * DMODEL + n) = hi;
        }
    }
}

// ============================================================
extern "C" void kernel_launch(void* const* d_in, const int* in_sizes, int n_in,
                              void* d_out, int out_size)
{
    const float* query = (const float*)d_in[0];
    const float* key   = (const float*)d_in[1];
    const float* value = (const float*)d_in[2];
    const float* Wq    = (const float*)d_in[3];
    const float* bq    = (const float*)d_in[4];
    const float* Wk    = (const float*)d_in[5];
    const float* bk    = (const float*)d_in[6];
    const float* Wv    = (const float*)d_in[7];
    const float* bv    = (const float*)d_in[8];

    float* out   = (float*)d_out;
    float* aten  = out;                                   // (S, B, D)
    float* probs = out + (size_t)SEQ * BATCH * DMODEL;    // (B, S, S)

    static int attr_set = 0;
    if (!attr_set) {
        cudaFuncSetAttribute(aten_mma_kernel,  cudaFuncAttributeMaxDynamicSharedMemorySize, GM_SMEM);
        cudaFuncSetAttribute(projv_mma_kernel, cudaFuncAttributeMaxDynamicSharedMemorySize, GM_SMEM);
        attr_set = 1;
    }

    // q/k projections fused (fp32)
    {
        dim3 grid(MTOT / 64, 2);
        projqk_kernel<<<grid, 256>>>(query, Wq, bq, key, Wk, bk);
    }

    // v projection via split mma GEMM
    xvsplit_kernel<<<(MTOT * DMODEL / 4) / 256, 256>>>(value);
    {
        dim3 grid(DMODEL / 32, DMODEL / 32);
        wvsplit_kernel<<<grid, 256>>>(Wv);
    }
    {
        dim3 grid(DMODEL / 128, MTOT / 128);
        projv_mma_kernel<<<grid, 512, GM_SMEM>>>(bv);
    }

    // v split+transpose to bf16 for aten
    {
        dim3 grid(DMODEL / 32, SEQ / 32, BATCH);
        vsplit_kernel<<<grid, 256>>>();
    }

    // scores GEMM -> raw scaled scores in probs region
    {
        dim3 grid(SEQ / 128, SEQ / 128, BATCH);
        scores_kernel<<<grid, 256>>>(probs);
    }

    // row softmax in place
    rowsoftmax_kernel<<<BATCH * SEQ, 256>>>(probs);

    // column sums + in-place renorm (+ emit bf16 split of probs)
    {
        dim3 grid(SEQ / 256, BATCH);
        colsum_kernel<<<grid, 256>>>(probs);
    }
    {
        size_t total4 = (size_t)BATCH * SEQ * SEQ / 4;
        renorm_split_kernel<<<(unsigned)(total4 / 256), 256>>>(probs);
    }

    // aten = probs @ v  via split mma GEMM
    {
        dim3 grid(DMODEL / 128, SEQ / 128, BATCH);
        aten_mma_kernel<<<grid, 512, GM_SMEM>>>(aten);
    }
}

// round 14
// speedup vs baseline: 1.1163x; 1.1163x over previous
#include <cuda_runtime.h>
#include <cuda_bf16.h>
#include <cstdint>

#define SEQ    2048
#define BATCH  4
#define DMODEL 1024
#define DINT   64
#define MTOT   (SEQ * BATCH)   // 8192
#define KP2    (2 * SEQ)       // 4096: [hi|lo] rows for aten operands
#define KPV2   (2 * DMODEL)    // 2048: [hi|lo] rows for projv operands
#define KQ2    (2 * DINT)      // 128:  [hi|lo] rows for q/k operands

// ---- scratch (device globals: allocation-free) ----
__device__ float g_v[BATCH * SEQ * DMODEL];
__device__ float g_colsum[BATCH * SEQ];
__device__ alignas(256) __nv_bfloat16 g_q2[(size_t)BATCH * SEQ * KQ2];     // q      [b][s][hi|lo]
__device__ alignas(256) __nv_bfloat16 g_k2[(size_t)BATCH * SEQ * KQ2];     // k      [b][s][hi|lo]
__device__ alignas(256) __nv_bfloat16 g_a2[(size_t)BATCH * SEQ * KP2];     // probs  [b][q][hi|lo]
__device__ alignas(256) __nv_bfloat16 g_b2[(size_t)BATCH * DMODEL * KP2];  // v^T    [b][n][hi|lo]
__device__ alignas(256) __nv_bfloat16 g_xv2[(size_t)MTOT * KPV2];          // value  [m][hi|lo]
__device__ alignas(256) __nv_bfloat16 g_wv2[(size_t)DMODEL * KPV2];        // Wv^T   [n][hi|lo]

// ================= baseline-ISA helpers =================
__device__ __forceinline__ uint32_t smem_u32(const void* p) {
    uint32_t a;
    asm("{ .reg .u64 t; cvta.to.shared.u64 t, %1; cvt.u32.u64 %0, t; }" : "=r"(a) : "l"(p));
    return a;
}
#define SMEM_SWIZZLE_128B(o) ((o) ^ (((o) >> 3) & 0x70))
#define CP_ASYNC16(dst, src) \
    asm volatile("cp.async.cg.shared.global [%0], [%1], 16;" :: "r"(dst), "l"(src) : "memory")
#define CP_COMMIT() asm volatile("cp.async.commit_group;" ::: "memory")
#define CP_WAIT(n)  asm volatile("cp.async.wait_group %0;" :: "n"(n) : "memory")
#define LDSM_X4(r0, r1, r2, r3, addr) \
    asm volatile("ldmatrix.sync.aligned.m8n8.x4.shared.b16 {%0,%1,%2,%3}, [%4];" \
        : "=r"(r0), "=r"(r1), "=r"(r2), "=r"(r3) : "r"(addr))
#define MMA16816(d, a0, a1, a2, a3, b0, b1) \
    asm volatile("mma.sync.aligned.m16n8k16.row.col.f32.bf16.bf16.f32 " \
        "{%0,%1,%2,%3}, {%4,%5,%6,%7}, {%8,%9}, {%0,%1,%2,%3};" \
        : "+f"((d)[0]), "+f"((d)[1]), "+f"((d)[2]), "+f"((d)[3]) \
        : "r"(a0), "r"(a1), "r"(a2), "r"(a3), "r"(b0), "r"(b1))

__device__ __forceinline__ void split2(float v, __nv_bfloat16& h, __nv_bfloat16& l) {
    h = __float2bfloat16(v);
    l = __float2bfloat16(v - __bfloat162float(h));
}

// ============================================================
// q+k projections fused: X(8192,1024) @ W(1024,64) + bias
// Emits split bf16 rows [hi|lo] directly to g_q2 / g_k2.
// ============================================================
__global__ void projqk_kernel(const float* __restrict__ Q,
                              const float* __restrict__ Wq,
                              const float* __restrict__ bq,
                              const float* __restrict__ Kin,
                              const float* __restrict__ Wk,
                              const float* __restrict__ bk)
{
    __shared__ float As[16][64];
    __shared__ float Bs[16][64];
    const int tid = threadIdx.x;
    const int tx = tid & 15, ty = tid >> 4;
    const int m0 = blockIdx.x * 64;
    const int which = blockIdx.y;
    const float* X    = which ? Kin : Q;
    const float* W    = which ? Wk  : Wq;
    const float* bias = which ? bk  : bq;
    __nv_bfloat16* out = which ? g_k2 : g_q2;

    float acc[4][4] = {};

    for (int k0 = 0; k0 < DMODEL; k0 += 16) {
        {
            int row = tid >> 2;
            int kg  = (tid & 3) * 4;
            float4 v = *reinterpret_cast<const float4*>(&X[(size_t)(m0 + row) * DMODEL + k0 + kg]);
            As[kg + 0][row] = v.x; As[kg + 1][row] = v.y;
            As[kg + 2][row] = v.z; As[kg + 3][row] = v.w;
        }
        {
            int row = tid >> 4;
            int col = (tid & 15) * 4;
            *reinterpret_cast<float4*>(&Bs[row][col]) =
                *reinterpret_cast<const float4*>(&W[(size_t)(k0 + row) * DINT + col]);
        }
        __syncthreads();
#pragma unroll
        for (int kk = 0; kk < 16; kk++) {
            float a[4], b[4];
#pragma unroll
            for (int i = 0; i < 4; i++) a[i] = As[kk][ty * 4 + i];
#pragma unroll
            for (int j = 0; j < 4; j++) b[j] = Bs[kk][tx * 4 + j];
#pragma unroll
            for (int i = 0; i < 4; i++)
#pragma unroll
                for (int j = 0; j < 4; j++) acc[i][j] += a[i] * b[j];
        }
        __syncthreads();
    }

#pragma unroll
    for (int i = 0; i < 4; i++) {
        int m = m0 + ty * 4 + i;
        int s = m >> 2, b = m & 3;
        __nv_bfloat16* orow = &out[(size_t)(b * SEQ + s) * KQ2];
#pragma unroll
        for (int j = 0; j < 4; j++) {
            int n = tx * 4 + j;
            float v = acc[i][j] + bias[n];
            __nv_bfloat16 h, l;
            split2(v, h, l);
            orow[n]        = h;
            orow[DINT + n] = l;
        }
    }
}

// ============================================================
// value split: value[m][k] -> g_xv2[m][ hi | lo ]
// ============================================================
__global__ void xvsplit_kernel(const float* __restrict__ X)
{
    size_t i4 = ((size_t)blockIdx.x * 256 + threadIdx.x) * 4;
    int k = (int)(i4 & (DMODEL - 1));
    int m = (int)(i4 >> 10);
    float4 p = *reinterpret_cast<const float4*>(&X[i4]);
    __nv_bfloat16 h0, h1, h2, h3, l0, l1, l2, l3;
    split2(p.x, h0, l0); split2(p.y, h1, l1);
    split2(p.z, h2, l2); split2(p.w, h3, l3);
    __nv_bfloat16* row = g_xv2 + (size_t)m * KPV2;
    __nv_bfloat162 ha; ha.x = h0; ha.y = h1;
    __nv_bfloat162 hb; hb.x = h2; hb.y = h3;
    __nv_bfloat162 la; la.x = l0; la.y = l1;
    __nv_bfloat162 lb; lb.x = l2; lb.y = l3;
    *reinterpret_cast<__nv_bfloat162*>(row + k)              = ha;
    *reinterpret_cast<__nv_bfloat162*>(row + k + 2)          = hb;
    *reinterpret_cast<__nv_bfloat162*>(row + DMODEL + k)     = la;
    *reinterpret_cast<__nv_bfloat162*>(row + DMODEL + k + 2) = lb;
}

// ============================================================
// Wv split+transpose: W[k][n] -> g_wv2[n][ hi | lo ]
// ============================================================
__global__ void wvsplit_kernel(const float* __restrict__ W)
{
    __shared__ float t[32][33];
    const int tid = threadIdx.x;
    const int n0 = blockIdx.x * 32;
    const int k0 = blockIdx.y * 32;

#pragma unroll
    for (int r = 0; r < 4; r++) {
        int idx = tid + r * 256;
        int kl = idx >> 5, nl = idx & 31;
        t[kl][nl] = W[(size_t)(k0 + kl) * DMODEL + n0 + nl];
    }
    __syncthreads();

#pragma unroll
    for (int r = 0; r < 2; r++) {
        int idx = tid + r * 256;
        int nl = idx >> 4;
        int kp = (idx & 15) * 2;
        float v0 = t[kp][nl], v1 = t[kp + 1][nl];
        __nv_bfloat16 h0, h1, l0, l1;
        split2(v0, h0, l0); split2(v1, h1, l1);
        __nv_bfloat16* row = g_wv2 + (size_t)(n0 + nl) * KPV2;
        __nv_bfloat162 hh; hh.x = h0; hh.y = h1;
        __nv_bfloat162 ll; ll.x = l0; ll.y = l1;
        *reinterpret_cast<__nv_bfloat162*>(row + k0 + kp)          = hh;
        *reinterpret_cast<__nv_bfloat162*>(row + DMODEL + k0 + kp) = ll;
    }
}

// ============================================================
// shared GEMM core (round-8 config: 256 thr / 8 warps, warp tile
// 32x64, single-buffer 4 tiles x 16KB, occ 2):
//   D[128,128] += Ahi*Bhi + Alo*Bhi + Ahi*Blo per 64-k chunk
// ============================================================
#define T_A_HI 0
#define T_A_LO 16384
#define T_B_HI 32768
#define T_B_LO 49152
#define GM_SMEM 65536

struct GemmAcc { float a[2][8][4]; };

__device__ __forceinline__ void gemm_split_mainloop(
    GemmAcc& g, uint32_t sbase,
    const __nv_bfloat16* Ag, const __nv_bfloat16* Bg,
    int kseg,   // hi/lo offset within a row
    int rowlen, // full row length (2*kseg)
    int nchunk, int tid, int wm, int wn, int lane)
{
#pragma unroll 1
    for (int c = 0; c < nchunk; c++) {
        const int k0 = c * 64;
        if (c > 0) __syncthreads();   // guard smem reuse
#pragma unroll
        for (int r = 0; r < 4; r++) {
            int idx = tid + r * 256;
            int row = idx >> 3, u = idx & 7;
            uint32_t off = SMEM_SWIZZLE_128B((uint32_t)(row * 128 + u * 16));
            const __nv_bfloat16* arow = Ag + (size_t)row * rowlen + k0 + u * 8;
            const __nv_bfloat16* brow = Bg + (size_t)row * rowlen + k0 + u * 8;
            CP_ASYNC16(sbase + T_A_HI + off, arow);
            CP_ASYNC16(sbase + T_A_LO + off, arow + kseg);
            CP_ASYNC16(sbase + T_B_HI + off, brow);
            CP_ASYNC16(sbase + T_B_LO + off, brow + kseg);
        }
        CP_COMMIT();
        CP_WAIT(0);
        __syncthreads();

#pragma unroll
        for (int kk = 0; kk < 4; kk++) {
            uint32_t af_h[8], af_l[8];
#pragma unroll
            for (int i = 0; i < 2; i++) {
                int row = wm * 32 + i * 16 + (lane & 15);
                uint32_t off = SMEM_SWIZZLE_128B(
                    (uint32_t)(row * 128 + kk * 32 + ((lane >> 4) & 1) * 16));
                LDSM_X4(af_h[i * 4 + 0], af_h[i * 4 + 1], af_h[i * 4 + 2], af_h[i * 4 + 3],
                        sbase + T_A_HI + off);
                LDSM_X4(af_l[i * 4 + 0], af_l[i * 4 + 1], af_l[i * 4 + 2], af_l[i * 4 + 3],
                        sbase + T_A_LO + off);
            }
#pragma unroll
            for (int pass = 0; pass < 2; pass++) {
                uint32_t bf[16];
                uint32_t tbase = sbase + (pass ? T_B_LO : T_B_HI);
#pragma unroll
                for (int j = 0; j < 4; j++) {
                    int row = wn * 64 + j * 16 + ((lane >> 1) & 8) + (lane & 7);
                    uint32_t off = SMEM_SWIZZLE_128B(
                        (uint32_t)(row * 128 + kk * 32 + ((lane >> 3) & 1) * 16));
                    LDSM_X4(bf[j * 4 + 0], bf[j * 4 + 1], bf[j * 4 + 2], bf[j * 4 + 3],
                            tbase + off);
                }
#pragma unroll
                for (int i = 0; i < 2; i++)
#pragma unroll
                    for (int j = 0; j < 8; j++) {
                        int bidx = (j >> 1) * 4 + (j & 1) * 2;
                        MMA16816(g.a[i][j],
                                 af_h[i * 4 + 0], af_h[i * 4 + 1], af_h[i * 4 + 2], af_h[i * 4 + 3],
                                 bf[bidx], bf[bidx + 1]);
                        if (pass == 0)
                            MMA16816(g.a[i][j],
                                     af_l[i * 4 + 0], af_l[i * 4 + 1], af_l[i * 4 + 2], af_l[i * 4 + 3],
                                     bf[bidx], bf[bidx + 1]);
                    }
            }
        }
    }
}

// ============================================================
// scores = q @ k^T * 0.125 via split mma (K'=64, 1 chunk)
// ============================================================
__global__ void __launch_bounds__(256, 2) scores_mma_kernel(float* __restrict__ probs)
{
    extern __shared__ char smem[];
    const int tid = threadIdx.x;
    const int wid = tid >> 5, lane = tid & 31;
    const int wm = wid & 3, wn = wid >> 2;
    const int b  = blockIdx.z;
    const int m0 = blockIdx.y * 128;
    const int n0 = blockIdx.x * 128;
    const uint32_t sbase = smem_u32(smem);

    GemmAcc g = {};
    gemm_split_mainloop(g, sbase,
                        g_q2 + (size_t)(b * SEQ + m0) * KQ2,
                        g_k2 + (size_t)(b * SEQ + n0) * KQ2,
                        DINT, KQ2, 1, tid, wm, wn, lane);

    float* C = probs + (size_t)b * SEQ * SEQ;
#pragma unroll
    for (int i = 0; i < 2; i++) {
        int row = m0 + wm * 32 + i * 16 + (lane >> 2);
#pragma unroll
        for (int j = 0; j < 8; j++) {
            int n = n0 + wn * 64 + j * 8 + (lane & 3) * 2;
            float2 lo = make_float2(g.a[i][j][0] * 0.125f, g.a[i][j][1] * 0.125f);
            float2 hi = make_float2(g.a[i][j][2] * 0.125f, g.a[i][j][3] * 0.125f);
            *reinterpret_cast<float2*>(C + (size_t)row * SEQ + n)       = lo;
            *reinterpret_cast<float2*>(C + (size_t)(row + 8) * SEQ + n) = hi;
        }
    }
}

// ============================================================
// projv: g_v = value @ Wv + bv   (M=8192, N=1024, K=1024 split)
// ============================================================
__global__ void __launch_bounds__(256, 2) projv_mma_kernel(const float* __restrict__ bias)
{
    extern __shared__ char smem[];
    const int tid = threadIdx.x;
    const int wid = tid >> 5, lane = tid & 31;
    const int wm = wid & 3, wn = wid >> 2;
    const int m0 = blockIdx.y * 128;
    const int n0 = blockIdx.x * 128;
    const uint32_t sbase = smem_u32(smem);

    GemmAcc g = {};
    gemm_split_mainloop(g, sbase,
                        g_xv2 + (size_t)m0 * KPV2,
                        g_wv2 + (size_t)n0 * KPV2,
                        DMODEL, KPV2, DMODEL / 64, tid, wm, wn, lane);

#pragma unroll
    for (int i = 0; i < 2; i++) {
        int m_a = m0 + wm * 32 + i * 16 + (lane >> 2);
        int m_b = m_a + 8;
        int sa = m_a >> 2, ba = m_a & 3;
        int sb = m_b >> 2, bb2 = m_b & 3;
#pragma unroll
        for (int j = 0; j < 8; j++) {
            int n = n0 + wn * 64 + j * 8 + (lane & 3) * 2;
            float2 bias2 = *reinterpret_cast<const float2*>(bias + n);
            float2 lo = make_float2(g.a[i][j][0] + bias2.x, g.a[i][j][1] + bias2.y);
            float2 hi = make_float2(g.a[i][j][2] + bias2.x, g.a[i][j][3] + bias2.y);
            *reinterpret_cast<float2*>(g_v + ((size_t)(ba * SEQ + sa)) * DMODEL + n)  = lo;
            *reinterpret_cast<float2*>(g_v + ((size_t)(bb2 * SEQ + sb)) * DMODEL + n) = hi;
        }
    }
}

// ============================================================
// v split+transpose: g_v[b][s][n] -> g_b2[b][n][ hi | lo ]
// ============================================================
__global__ void vsplit_kernel()
{
    __shared__ float t[32][33];
    const int tid = threadIdx.x;
    const int b  = blockIdx.z;
    const int n0 = blockIdx.x * 32;
    const int s0 = blockIdx.y * 32;

#pragma unroll
    for (int r = 0; r < 4; r++) {
        int idx = tid + r * 256;
        int sl = idx >> 5, nl = idx & 31;
        t[sl][nl] = g_v[((size_t)(b * SEQ + s0 + sl)) * DMODEL + n0 + nl];
    }
    __syncthreads();

#pragma unroll
    for (int r = 0; r < 2; r++) {
        int idx = tid + r * 256;
        int nl = idx >> 4;
        int sp = (idx & 15) * 2;
        float v0 = t[sp][nl], v1 = t[sp + 1][nl];
        __nv_bfloat16 h0, h1, l0, l1;
        split2(v0, h0, l0); split2(v1, h1, l1);
        __nv_bfloat16* row = g_b2 + ((size_t)(b * DMODEL + n0 + nl)) * KP2;
        __nv_bfloat162 hh; hh.x = h0; hh.y = h1;
        __nv_bfloat162 ll; ll.x = l0; ll.y = l1;
        *reinterpret_cast<__nv_bfloat162*>(row + s0 + sp)       = hh;
        *reinterpret_cast<__nv_bfloat162*>(row + SEQ + s0 + sp) = ll;
    }
}

// ============================================================
// row softmax in place
// ============================================================
__global__ void rowsoftmax_kernel(float* __restrict__ probs)
{
    const int tid = threadIdx.x;
    float* p = probs + (size_t)blockIdx.x * SEQ;

    __shared__ float red[8];

    float4 v0 = reinterpret_cast<float4*>(p)[tid];
    float4 v1 = reinterpret_cast<float4*>(p)[tid + 256];

    float mx = fmaxf(fmaxf(fmaxf(v0.x, v0.y), fmaxf(v0.z, v0.w)),
                     fmaxf(fmaxf(v1.x, v1.y), fmaxf(v1.z, v1.w)));
#pragma unroll
    for (int o = 16; o > 0; o >>= 1)
        mx = fmaxf(mx, __shfl_xor_sync(0xffffffffu, mx, o));
    if ((tid & 31) == 0) red[tid >> 5] = mx;
    __syncthreads();
    {
        float m = red[tid & 7];
#pragma unroll
        for (int o = 4; o > 0; o >>= 1)
            m = fmaxf(m, __shfl_xor_sync(0xffffffffu, m, o));
        mx = m;
    }

    v0.x = __expf(v0.x - mx); v0.y = __expf(v0.y - mx);
    v0.z = __expf(v0.z - mx); v0.w = __expf(v0.w - mx);
    v1.x = __expf(v1.x - mx); v1.y = __expf(v1.y - mx);
    v1.z = __expf(v1.z - mx); v1.w = __expf(v1.w - mx);

    float sum = v0.x + v0.y + v0.z + v0.w + v1.x + v1.y + v1.z + v1.w;
#pragma unroll
    for (int o = 16; o > 0; o >>= 1)
        sum += __shfl_xor_sync(0xffffffffu, sum, o);
    __syncthreads();
    if ((tid & 31) == 0) red[tid >> 5] = sum;
    __syncthreads();
    {
        float s = red[tid & 7];
#pragma unroll
        for (int o = 4; o > 0; o >>= 1)
            s += __shfl_xor_sync(0xffffffffu, s, o);
        sum = s;
    }
    float inv = 1.0f / sum;

    v0.x *= inv; v0.y *= inv; v0.z *= inv; v0.w *= inv;
    v1.x *= inv; v1.y *= inv; v1.z *= inv; v1.w *= inv;
    reinterpret_cast<float4*>(p)[tid]       = v0;
    reinterpret_cast<float4*>(p)[tid + 256] = v1;
}

// ============================================================
// column sums over q
// ============================================================
__global__ void colsum_kernel(const float* __restrict__ probs)
{
    const int k = blockIdx.x * 256 + threadIdx.x;
    const int b = blockIdx.y;
    const float* p = probs + (size_t)b * SEQ * SEQ + k;
    float s = 0.f;
    for (int q = 0; q < SEQ; q++) s += p[(size_t)q * SEQ];
    g_colsum[b * SEQ + k] = s;
}

// ============================================================
// renorm in place + emit bf16 split A2 = [hi | lo]
// ============================================================
__global__ void renorm_split_kernel(float* __restrict__ probs)
{
    size_t i4 = ((size_t)blockIdx.x * 256 + threadIdx.x) * 4;
    int k = (int)(i4 & (SEQ - 1));
    int q = (int)((i4 >> 11) & (SEQ - 1));
    int b = (int)(i4 >> 22);
    float4 p = *reinterpret_cast<float4*>(&probs[i4]);
    const float4 c = *reinterpret_cast<const float4*>(&g_colsum[b * SEQ + k]);
    p.x /= (1e-9f + c.x);
    p.y /= (1e-9f + c.y);
    p.z /= (1e-9f + c.z);
    p.w /= (1e-9f + c.w);
    *reinterpret_cast<float4*>(&probs[i4]) = p;

    __nv_bfloat16 h0, h1, h2, h3, l0, l1, l2, l3;
    split2(p.x, h0, l0); split2(p.y, h1, l1);
    split2(p.z, h2, l2); split2(p.w, h3, l3);

    __nv_bfloat16* row = g_a2 + ((size_t)(b * SEQ + q)) * KP2;
    __nv_bfloat162 ha; ha.x = h0; ha.y = h1;
    __nv_bfloat162 hb; hb.x = h2; hb.y = h3;
    __nv_bfloat162 la; la.x = l0; la.y = l1;
    __nv_bfloat162 lb; lb.x = l2; lb.y = l3;
    *reinterpret_cast<__nv_bfloat162*>(row + k)           = ha;
    *reinterpret_cast<__nv_bfloat162*>(row + k + 2)       = hb;
    *reinterpret_cast<__nv_bfloat162*>(row + SEQ + k)     = la;
    *reinterpret_cast<__nv_bfloat162*>(row + SEQ + k + 2) = lb;
}

// ============================================================
// aten: out = probs @ v   (per batch 2048x1024, K=2048 split)
// ============================================================
__global__ void __launch_bounds__(256, 2) aten_mma_kernel(float* __restrict__ out)
{
    extern __shared__ char smem[];
    const int tid = threadIdx.x;
    const int wid = tid >> 5, lane = tid & 31;
    const int wm = wid & 3, wn = wid >> 2;
    const int b  = blockIdx.z;
    const int m0 = blockIdx.y * 128;
    const int n0 = blockIdx.x * 128;
    const uint32_t sbase = smem_u32(smem);

    GemmAcc g = {};
    gemm_split_mainloop(g, sbase,
                        g_a2 + (size_t)b * SEQ * KP2 + (size_t)m0 * KP2,
                        g_b2 + (size_t)b * DMODEL * KP2 + (size_t)n0 * KP2,
                        SEQ, KP2, SEQ / 64, tid, wm, wn, lane);

#pragma unroll
    for (int i = 0; i < 2; i++) {
        int q = m0 + wm * 32 + i * 16 + (lane >> 2);
#pragma unroll
        for (int j = 0; j < 8; j++) {
            int n = n0 + wn * 64 + j * 8 + (lane & 3) * 2;
            float2 lo = make_float2(g.a[i][j][0], g.a[i][j][1]);
            float2 hi = make_float2(g.a[i][j][2], g.a[i][j][3]);
            *reinterpret_cast<float2*>(out + ((size_t)q * BATCH + b) * DMODEL + n)       = lo;
            *reinterpret_cast<float2*>(out + ((size_t)(q + 8) * BATCH + b) * DMODEL + n) = hi;
        }
    }
}

// ============================================================
extern "C" void kernel_launch(void* const* d_in, const int* in_sizes, int n_in,
                              void* d_out, int out_size)
{
    const float* query = (const float*)d_in[0];
    const float* key   = (const float*)d_in[1];
    const float* value = (const float*)d_in[2];
    const float* Wq    = (const float*)d_in[3];
    const float* bq    = (const float*)d_in[4];
    const float* Wk    = (const float*)d_in[5];
    const float* bk    = (const float*)d_in[6];
    const float* Wv    = (const float*)d_in[7];
    const float* bv    = (const float*)d_in[8];

    float* out   = (float*)d_out;
    float* aten  = out;                                   // (S, B, D)
    float* probs = out + (size_t)SEQ * BATCH * DMODEL;    // (B, S, S)

    static int attr_set = 0;
    if (!attr_set) {
        cudaFuncSetAttribute(aten_mma_kernel,   cudaFuncAttributeMaxDynamicSharedMemorySize, GM_SMEM);
        cudaFuncSetAttribute(projv_mma_kernel,  cudaFuncAttributeMaxDynamicSharedMemorySize, GM_SMEM);
        cudaFuncSetAttribute(scores_mma_kernel, cudaFuncAttributeMaxDynamicSharedMemorySize, GM_SMEM);
        attr_set = 1;
    }

    // q/k projections (fp32 compute, split bf16 emit)
    {
        dim3 grid(MTOT / 64, 2);
        projqk_kernel<<<grid, 256>>>(query, Wq, bq, key, Wk, bk);
    }

    // v projection via split mma GEMM
    xvsplit_kernel<<<(MTOT * DMODEL / 4) / 256, 256>>>(value);
    {
        dim3 grid(DMODEL / 32, DMODEL / 32);
        wvsplit_kernel<<<grid, 256>>>(Wv);
    }
    {
        dim3 grid(DMODEL / 128, MTOT / 128);
        projv_mma_kernel<<<grid, 256, GM_SMEM>>>(bv);
    }

    // v split+transpose to bf16 for aten
    {
        dim3 grid(DMODEL / 32, SEQ / 32, BATCH);
        vsplit_kernel<<<grid, 256>>>();
    }

    // scores via split mma GEMM -> raw scaled scores in probs region
    {
        dim3 grid(SEQ / 128, SEQ / 128, BATCH);
        scores_mma_kernel<<<grid, 256, GM_SMEM>>>(probs);
    }

    // row softmax in place
    rowsoftmax_kernel<<<BATCH * SEQ, 256>>>(probs);

    // column sums + in-place renorm (+ emit bf16 split of probs)
    {
        dim3 grid(SEQ / 256, BATCH);
        colsum_kernel<<<grid, 256>>>(probs);
    }
    {
        size_t total4 = (size_t)BATCH * SEQ * SEQ / 4;
        renorm_split_kernel<<<(unsigned)(total4 / 256), 256>>>(probs);
    }

    // aten = probs @ v  via split mma GEMM
    {
        dim3 grid(DMODEL / 128, SEQ / 128, BATCH);
        aten_mma_kernel<<<grid, 256, GM_SMEM>>>(aten);
    }
}

// round 15
// speedup vs baseline: 1.1618x; 1.0407x over previous
#include <cuda_runtime.h>
#include <cuda_bf16.h>
#include <cstdint>

#define SEQ    2048
#define BATCH  4
#define DMODEL 1024
#define DINT   64
#define MTOT   (SEQ * BATCH)   // 8192
#define KP2    (2 * SEQ)       // 4096: [hi|lo] rows for aten operands
#define KPV2   (2 * DMODEL)    // 2048: [hi|lo] rows for projv operands
#define KQ2    (2 * DINT)      // 128:  [hi|lo] rows for q/k operands
#define QCHUNK 16              // colsum partial chunks

// ---- scratch (device globals: allocation-free) ----
__device__ float g_v[BATCH * SEQ * DMODEL];
__device__ float g_colsum[BATCH * SEQ];
__device__ float g_cs_part[QCHUNK * BATCH * SEQ];
__device__ alignas(256) __nv_bfloat16 g_q2[(size_t)BATCH * SEQ * KQ2];     // q      [b][s][hi|lo]
__device__ alignas(256) __nv_bfloat16 g_k2[(size_t)BATCH * SEQ * KQ2];     // k      [b][s][hi|lo]
__device__ alignas(256) __nv_bfloat16 g_a2[(size_t)BATCH * SEQ * KP2];     // probs  [b][q][hi|lo]
__device__ alignas(256) __nv_bfloat16 g_b2[(size_t)BATCH * DMODEL * KP2];  // v^T    [b][n][hi|lo]
__device__ alignas(256) __nv_bfloat16 g_xv2[(size_t)MTOT * KPV2];          // value  [m][hi|lo]
__device__ alignas(256) __nv_bfloat16 g_wv2[(size_t)DMODEL * KPV2];        // Wv^T   [n][hi|lo]

// ================= baseline-ISA helpers =================
__device__ __forceinline__ uint32_t smem_u32(const void* p) {
    uint32_t a;
    asm("{ .reg .u64 t; cvta.to.shared.u64 t, %1; cvt.u32.u64 %0, t; }" : "=r"(a) : "l"(p));
    return a;
}
#define SMEM_SWIZZLE_128B(o) ((o) ^ (((o) >> 3) & 0x70))
#define CP_ASYNC16(dst, src) \
    asm volatile("cp.async.cg.shared.global [%0], [%1], 16;" :: "r"(dst), "l"(src) : "memory")
#define CP_COMMIT() asm volatile("cp.async.commit_group;" ::: "memory")
#define CP_WAIT(n)  asm volatile("cp.async.wait_group %0;" :: "n"(n) : "memory")
#define LDSM_X4(r0, r1, r2, r3, addr) \
    asm volatile("ldmatrix.sync.aligned.m8n8.x4.shared.b16 {%0,%1,%2,%3}, [%4];" \
        : "=r"(r0), "=r"(r1), "=r"(r2), "=r"(r3) : "r"(addr))
#define MMA16816(d, a0, a1, a2, a3, b0, b1) \
    asm volatile("mma.sync.aligned.m16n8k16.row.col.f32.bf16.bf16.f32 " \
        "{%0,%1,%2,%3}, {%4,%5,%6,%7}, {%8,%9}, {%0,%1,%2,%3};" \
        : "+f"((d)[0]), "+f"((d)[1]), "+f"((d)[2]), "+f"((d)[3]) \
        : "r"(a0), "r"(a1), "r"(a2), "r"(a3), "r"(b0), "r"(b1))

__device__ __forceinline__ void split2(float v, __nv_bfloat16& h, __nv_bfloat16& l) {
    h = __float2bfloat16(v);
    l = __float2bfloat16(v - __bfloat162float(h));
}

// ============================================================
// q+k projections fused: X(8192,1024) @ W(1024,64) + bias
// Emits split bf16 rows [hi|lo] directly to g_q2 / g_k2.
// ============================================================
__global__ void projqk_kernel(const float* __restrict__ Q,
                              const float* __restrict__ Wq,
                              const float* __restrict__ bq,
                              const float* __restrict__ Kin,
                              const float* __restrict__ Wk,
                              const float* __restrict__ bk)
{
    __shared__ float As[16][64];
    __shared__ float Bs[16][64];
    const int tid = threadIdx.x;
    const int tx = tid & 15, ty = tid >> 4;
    const int m0 = blockIdx.x * 64;
    const int which = blockIdx.y;
    const float* X    = which ? Kin : Q;
    const float* W    = which ? Wk  : Wq;
    const float* bias = which ? bk  : bq;
    __nv_bfloat16* out = which ? g_k2 : g_q2;

    float acc[4][4] = {};

    for (int k0 = 0; k0 < DMODEL; k0 += 16) {
        {
            int row = tid >> 2;
            int kg  = (tid & 3) * 4;
            float4 v = *reinterpret_cast<const float4*>(&X[(size_t)(m0 + row) * DMODEL + k0 + kg]);
            As[kg + 0][row] = v.x; As[kg + 1][row] = v.y;
            As[kg + 2][row] = v.z; As[kg + 3][row] = v.w;
        }
        {
            int row = tid >> 4;
            int col = (tid & 15) * 4;
            *reinterpret_cast<float4*>(&Bs[row][col]) =
                *reinterpret_cast<const float4*>(&W[(size_t)(k0 + row) * DINT + col]);
        }
        __syncthreads();
#pragma unroll
        for (int kk = 0; kk < 16; kk++) {
            float a[4], b[4];
#pragma unroll
            for (int i = 0; i < 4; i++) a[i] = As[kk][ty * 4 + i];
#pragma unroll
            for (int j = 0; j < 4; j++) b[j] = Bs[kk][tx * 4 + j];
#pragma unroll
            for (int i = 0; i < 4; i++)
#pragma unroll
                for (int j = 0; j < 4; j++) acc[i][j] += a[i] * b[j];
        }
        __syncthreads();
    }

#pragma unroll
    for (int i = 0; i < 4; i++) {
        int m = m0 + ty * 4 + i;
        int s = m >> 2, b = m & 3;
        __nv_bfloat16* orow = &out[(size_t)(b * SEQ + s) * KQ2];
#pragma unroll
        for (int j = 0; j < 4; j++) {
            int n = tx * 4 + j;
            float v = acc[i][j] + bias[n];
            __nv_bfloat16 h, l;
            split2(v, h, l);
            orow[n]        = h;
            orow[DINT + n] = l;
        }
    }
}

// ============================================================
// value split: value[m][k] -> g_xv2[m][ hi | lo ]
// ============================================================
__global__ void xvsplit_kernel(const float* __restrict__ X)
{
    size_t i4 = ((size_t)blockIdx.x * 256 + threadIdx.x) * 4;
    int k = (int)(i4 & (DMODEL - 1));
    int m = (int)(i4 >> 10);
    float4 p = *reinterpret_cast<const float4*>(&X[i4]);
    __nv_bfloat16 h0, h1, h2, h3, l0, l1, l2, l3;
    split2(p.x, h0, l0); split2(p.y, h1, l1);
    split2(p.z, h2, l2); split2(p.w, h3, l3);
    __nv_bfloat16* row = g_xv2 + (size_t)m * KPV2;
    __nv_bfloat162 ha; ha.x = h0; ha.y = h1;
    __nv_bfloat162 hb; hb.x = h2; hb.y = h3;
    __nv_bfloat162 la; la.x = l0; la.y = l1;
    __nv_bfloat162 lb; lb.x = l2; lb.y = l3;
    *reinterpret_cast<__nv_bfloat162*>(row + k)              = ha;
    *reinterpret_cast<__nv_bfloat162*>(row + k + 2)          = hb;
    *reinterpret_cast<__nv_bfloat162*>(row + DMODEL + k)     = la;
    *reinterpret_cast<__nv_bfloat162*>(row + DMODEL + k + 2) = lb;
}

// ============================================================
// Wv split+transpose: W[k][n] -> g_wv2[n][ hi | lo ]
// ============================================================
__global__ void wvsplit_kernel(const float* __restrict__ W)
{
    __shared__ float t[32][33];
    const int tid = threadIdx.x;
    const int n0 = blockIdx.x * 32;
    const int k0 = blockIdx.y * 32;

#pragma unroll
    for (int r = 0; r < 4; r++) {
        int idx = tid + r * 256;
        int kl = idx >> 5, nl = idx & 31;
        t[kl][nl] = W[(size_t)(k0 + kl) * DMODEL + n0 + nl];
    }
    __syncthreads();

#pragma unroll
    for (int r = 0; r < 2; r++) {
        int idx = tid + r * 256;
        int nl = idx >> 4;
        int kp = (idx & 15) * 2;
        float v0 = t[kp][nl], v1 = t[kp + 1][nl];
        __nv_bfloat16 h0, h1, l0, l1;
        split2(v0, h0, l0); split2(v1, h1, l1);
        __nv_bfloat16* row = g_wv2 + (size_t)(n0 + nl) * KPV2;
        __nv_bfloat162 hh; hh.x = h0; hh.y = h1;
        __nv_bfloat162 ll; ll.x = l0; ll.y = l1;
        *reinterpret_cast<__nv_bfloat162*>(row + k0 + kp)          = hh;
        *reinterpret_cast<__nv_bfloat162*>(row + DMODEL + k0 + kp) = ll;
    }
}

// ============================================================
// shared GEMM core (round-8 config + MMA dependency reorder):
// 256 thr / 8 warps, warp tile 32x64, single-buffer 4x16KB, occ 2.
// Per k-step, three independent 16-MMA sweeps:
//   sweep1: acc += Ahi*Bhi   sweep2: acc += Alo*Bhi   sweep3: acc += Ahi*Blo
// (no back-to-back dependent MMAs on the same accumulator)
// ============================================================
#define T_A_HI 0
#define T_A_LO 16384
#define T_B_HI 32768
#define T_B_LO 49152
#define GM_SMEM 65536

struct GemmAcc { float a[2][8][4]; };

__device__ __forceinline__ void gemm_split_mainloop(
    GemmAcc& g, uint32_t sbase,
    const __nv_bfloat16* Ag, const __nv_bfloat16* Bg,
    int kseg,   // hi/lo offset within a row
    int rowlen, // full row length (2*kseg)
    int nchunk, int tid, int wm, int wn, int lane)
{
#pragma unroll 1
    for (int c = 0; c < nchunk; c++) {
        const int k0 = c * 64;
        if (c > 0) __syncthreads();   // guard smem reuse
#pragma unroll
        for (int r = 0; r < 4; r++) {
            int idx = tid + r * 256;
            int row = idx >> 3, u = idx & 7;
            uint32_t off = SMEM_SWIZZLE_128B((uint32_t)(row * 128 + u * 16));
            const __nv_bfloat16* arow = Ag + (size_t)row * rowlen + k0 + u * 8;
            const __nv_bfloat16* brow = Bg + (size_t)row * rowlen + k0 + u * 8;
            CP_ASYNC16(sbase + T_A_HI + off, arow);
            CP_ASYNC16(sbase + T_A_LO + off, arow + kseg);
            CP_ASYNC16(sbase + T_B_HI + off, brow);
            CP_ASYNC16(sbase + T_B_LO + off, brow + kseg);
        }
        CP_COMMIT();
        CP_WAIT(0);
        __syncthreads();

#pragma unroll
        for (int kk = 0; kk < 4; kk++) {
            uint32_t af_h[8], af_l[8];
#pragma unroll
            for (int i = 0; i < 2; i++) {
                int row = wm * 32 + i * 16 + (lane & 15);
                uint32_t off = SMEM_SWIZZLE_128B(
                    (uint32_t)(row * 128 + kk * 32 + ((lane >> 4) & 1) * 16));
                LDSM_X4(af_h[i * 4 + 0], af_h[i * 4 + 1], af_h[i * 4 + 2], af_h[i * 4 + 3],
                        sbase + T_A_HI + off);
                LDSM_X4(af_l[i * 4 + 0], af_l[i * 4 + 1], af_l[i * 4 + 2], af_l[i * 4 + 3],
                        sbase + T_A_LO + off);
            }
            // B_hi fragments
            uint32_t bf[16];
#pragma unroll
            for (int j = 0; j < 4; j++) {
                int row = wn * 64 + j * 16 + ((lane >> 1) & 8) + (lane & 7);
                uint32_t off = SMEM_SWIZZLE_128B(
                    (uint32_t)(row * 128 + kk * 32 + ((lane >> 3) & 1) * 16));
                LDSM_X4(bf[j * 4 + 0], bf[j * 4 + 1], bf[j * 4 + 2], bf[j * 4 + 3],
                        sbase + T_B_HI + off);
            }
            // sweep 1: Ahi * Bhi (16 independent MMAs)
#pragma unroll
            for (int i = 0; i < 2; i++)
#pragma unroll
                for (int j = 0; j < 8; j++) {
                    int bidx = (j >> 1) * 4 + (j & 1) * 2;
                    MMA16816(g.a[i][j],
                             af_h[i * 4 + 0], af_h[i * 4 + 1], af_h[i * 4 + 2], af_h[i * 4 + 3],
                             bf[bidx], bf[bidx + 1]);
                }
            // sweep 2: Alo * Bhi (16 independent MMAs)
#pragma unroll
            for (int i = 0; i < 2; i++)
#pragma unroll
                for (int j = 0; j < 8; j++) {
                    int bidx = (j >> 1) * 4 + (j & 1) * 2;
                    MMA16816(g.a[i][j],
                             af_l[i * 4 + 0], af_l[i * 4 + 1], af_l[i * 4 + 2], af_l[i * 4 + 3],
                             bf[bidx], bf[bidx + 1]);
                }
            // B_lo fragments (reuse bf regs)
#pragma unroll
            for (int j = 0; j < 4; j++) {
                int row = wn * 64 + j * 16 + ((lane >> 1) & 8) + (lane & 7);
                uint32_t off = SMEM_SWIZZLE_128B(
                    (uint32_t)(row * 128 + kk * 32 + ((lane >> 3) & 1) * 16));
                LDSM_X4(bf[j * 4 + 0], bf[j * 4 + 1], bf[j * 4 + 2], bf[j * 4 + 3],
                        sbase + T_B_LO + off);
            }
            // sweep 3: Ahi * Blo (16 independent MMAs)
#pragma unroll
            for (int i = 0; i < 2; i++)
#pragma unroll
                for (int j = 0; j < 8; j++) {
                    int bidx = (j >> 1) * 4 + (j & 1) * 2;
                    MMA16816(g.a[i][j],
                             af_h[i * 4 + 0], af_h[i * 4 + 1], af_h[i * 4 + 2], af_h[i * 4 + 3],
                             bf[bidx], bf[bidx + 1]);
                }
        }
    }
}

// ============================================================
// scores = q @ k^T * 0.125 via split mma (K'=64, 1 chunk)
// ============================================================
__global__ void __launch_bounds__(256, 2) scores_mma_kernel(float* __restrict__ probs)
{
    extern __shared__ char smem[];
    const int tid = threadIdx.x;
    const int wid = tid >> 5, lane = tid & 31;
    const int wm = wid & 3, wn = wid >> 2;
    const int b  = blockIdx.z;
    const int m0 = blockIdx.y * 128;
    const int n0 = blockIdx.x * 128;
    const uint32_t sbase = smem_u32(smem);

    GemmAcc g = {};
    gemm_split_mainloop(g, sbase,
                        g_q2 + (size_t)(b * SEQ + m0) * KQ2,
                        g_k2 + (size_t)(b * SEQ + n0) * KQ2,
                        DINT, KQ2, 1, tid, wm, wn, lane);

    float* C = probs + (size_t)b * SEQ * SEQ;
#pragma unroll
    for (int i = 0; i < 2; i++) {
        int row = m0 + wm * 32 + i * 16 + (lane >> 2);
#pragma unroll
        for (int j = 0; j < 8; j++) {
            int n = n0 + wn * 64 + j * 8 + (lane & 3) * 2;
            float2 lo = make_float2(g.a[i][j][0] * 0.125f, g.a[i][j][1] * 0.125f);
            float2 hi = make_float2(g.a[i][j][2] * 0.125f, g.a[i][j][3] * 0.125f);
            *reinterpret_cast<float2*>(C + (size_t)row * SEQ + n)       = lo;
            *reinterpret_cast<float2*>(C + (size_t)(row + 8) * SEQ + n) = hi;
        }
    }
}

// ============================================================
// projv: g_v = value @ Wv + bv   (M=8192, N=1024, K=1024 split)
// ============================================================
__global__ void __launch_bounds__(256, 2) projv_mma_kernel(const float* __restrict__ bias)
{
    extern __shared__ char smem[];
    const int tid = threadIdx.x;
    const int wid = tid >> 5, lane = tid & 31;
    const int wm = wid & 3, wn = wid >> 2;
    const int m0 = blockIdx.y * 128;
    const int n0 = blockIdx.x * 128;
    const uint32_t sbase = smem_u32(smem);

    GemmAcc g = {};
    gemm_split_mainloop(g, sbase,
                        g_xv2 + (size_t)m0 * KPV2,
                        g_wv2 + (size_t)n0 * KPV2,
                        DMODEL, KPV2, DMODEL / 64, tid, wm, wn, lane);

#pragma unroll
    for (int i = 0; i < 2; i++) {
        int m_a = m0 + wm * 32 + i * 16 + (lane >> 2);
        int m_b = m_a + 8;
        int sa = m_a >> 2, ba = m_a & 3;
        int sb = m_b >> 2, bb2 = m_b & 3;
#pragma unroll
        for (int j = 0; j < 8; j++) {
            int n = n0 + wn * 64 + j * 8 + (lane & 3) * 2;
            float2 bias2 = *reinterpret_cast<const float2*>(bias + n);
            float2 lo = make_float2(g.a[i][j][0] + bias2.x, g.a[i][j][1] + bias2.y);
            float2 hi = make_float2(g.a[i][j][2] + bias2.x, g.a[i][j][3] + bias2.y);
            *reinterpret_cast<float2*>(g_v + ((size_t)(ba * SEQ + sa)) * DMODEL + n)  = lo;
            *reinterpret_cast<float2*>(g_v + ((size_t)(bb2 * SEQ + sb)) * DMODEL + n) = hi;
        }
    }
}

// ============================================================
// v split+transpose: g_v[b][s][n] -> g_b2[b][n][ hi | lo ]
// ============================================================
__global__ void vsplit_kernel()
{
    __shared__ float t[32][33];
    const int tid = threadIdx.x;
    const int b  = blockIdx.z;
    const int n0 = blockIdx.x * 32;
    const int s0 = blockIdx.y * 32;

#pragma unroll
    for (int r = 0; r < 4; r++) {
        int idx = tid + r * 256;
        int sl = idx >> 5, nl = idx & 31;
        t[sl][nl] = g_v[((size_t)(b * SEQ + s0 + sl)) * DMODEL + n0 + nl];
    }
    __syncthreads();

#pragma unroll
    for (int r = 0; r < 2; r++) {
        int idx = tid + r * 256;
        int nl = idx >> 4;
        int sp = (idx & 15) * 2;
        float v0 = t[sp][nl], v1 = t[sp + 1][nl];
        __nv_bfloat16 h0, h1, l0, l1;
        split2(v0, h0, l0); split2(v1, h1, l1);
        __nv_bfloat16* row = g_b2 + ((size_t)(b * DMODEL + n0 + nl)) * KP2;
        __nv_bfloat162 hh; hh.x = h0; hh.y = h1;
        __nv_bfloat162 ll; ll.x = l0; ll.y = l1;
        *reinterpret_cast<__nv_bfloat162*>(row + s0 + sp)       = hh;
        *reinterpret_cast<__nv_bfloat162*>(row + SEQ + s0 + sp) = ll;
    }
}

// ============================================================
// row softmax in place
// ============================================================
__global__ void rowsoftmax_kernel(float* __restrict__ probs)
{
    const int tid = threadIdx.x;
    float* p = probs + (size_t)blockIdx.x * SEQ;

    __shared__ float red[8];

    float4 v0 = reinterpret_cast<float4*>(p)[tid];
    float4 v1 = reinterpret_cast<float4*>(p)[tid + 256];

    float mx = fmaxf(fmaxf(fmaxf(v0.x, v0.y), fmaxf(v0.z, v0.w)),
                     fmaxf(fmaxf(v1.x, v1.y), fmaxf(v1.z, v1.w)));
#pragma unroll
    for (int o = 16; o > 0; o >>= 1)
        mx = fmaxf(mx, __shfl_xor_sync(0xffffffffu, mx, o));
    if ((tid & 31) == 0) red[tid >> 5] = mx;
    __syncthreads();
    {
        float m = red[tid & 7];
#pragma unroll
        for (int o = 4; o > 0; o >>= 1)
            m = fmaxf(m, __shfl_xor_sync(0xffffffffu, m, o));
        mx = m;
    }

    v0.x = __expf(v0.x - mx); v0.y = __expf(v0.y - mx);
    v0.z = __expf(v0.z - mx); v0.w = __expf(v0.w - mx);
    v1.x = __expf(v1.x - mx); v1.y = __expf(v1.y - mx);
    v1.z = __expf(v1.z - mx); v1.w = __expf(v1.w - mx);

    float sum = v0.x + v0.y + v0.z + v0.w + v1.x + v1.y + v1.z + v1.w;
#pragma unroll
    for (int o = 16; o > 0; o >>= 1)
        sum += __shfl_xor_sync(0xffffffffu, sum, o);
    __syncthreads();
    if ((tid & 31) == 0) red[tid >> 5] = sum;
    __syncthreads();
    {
        float s = red[tid & 7];
#pragma unroll
        for (int o = 4; o > 0; o >>= 1)
            s += __shfl_xor_sync(0xffffffffu, s, o);
        sum = s;
    }
    float inv = 1.0f / sum;

    v0.x *= inv; v0.y *= inv; v0.z *= inv; v0.w *= inv;
    v1.x *= inv; v1.y *= inv; v1.z *= inv; v1.w *= inv;
    reinterpret_cast<float4*>(p)[tid]       = v0;
    reinterpret_cast<float4*>(p)[tid + 256] = v1;
}

// ============================================================
// column sums (two stage): partials over 128-row chunks, then reduce
// ============================================================
__global__ void colsum1_kernel(const float* __restrict__ probs)
{
    const int k  = blockIdx.x * 256 + threadIdx.x;
    const int b  = blockIdx.y;
    const int qc = blockIdx.z;
    const float* p = probs + (size_t)b * SEQ * SEQ + (size_t)qc * 128 * SEQ + k;
    float s = 0.f;
#pragma unroll 4
    for (int q = 0; q < 128; q++) s += p[(size_t)q * SEQ];
    g_cs_part[(size_t)(qc * BATCH + b) * SEQ + k] = s;
}

__global__ void colsum2_kernel()
{
    const int i = blockIdx.x * 256 + threadIdx.x;   // over BATCH*SEQ
    float s = 0.f;
#pragma unroll
    for (int c = 0; c < QCHUNK; c++) s += g_cs_part[(size_t)c * BATCH * SEQ + i];
    g_colsum[i] = s;
}

// ============================================================
// renorm in place + emit bf16 split A2 = [hi | lo]
// ============================================================
__global__ void renorm_split_kernel(float* __restrict__ probs)
{
    size_t i4 = ((size_t)blockIdx.x * 256 + threadIdx.x) * 4;
    int k = (int)(i4 & (SEQ - 1));
    int q = (int)((i4 >> 11) & (SEQ - 1));
    int b = (int)(i4 >> 22);
    float4 p = *reinterpret_cast<float4*>(&probs[i4]);
    const float4 c = *reinterpret_cast<const float4*>(&g_colsum[b * SEQ + k]);
    p.x /= (1e-9f + c.x);
    p.y /= (1e-9f + c.y);
    p.z /= (1e-9f + c.z);
    p.w /= (1e-9f + c.w);
    *reinterpret_cast<float4*>(&probs[i4]) = p;

    __nv_bfloat16 h0, h1, h2, h3, l0, l1, l2, l3;
    split2(p.x, h0, l0); split2(p.y, h1, l1);
    split2(p.z, h2, l2); split2(p.w, h3, l3);

    __nv_bfloat16* row = g_a2 + ((size_t)(b * SEQ + q)) * KP2;
    __nv_bfloat162 ha; ha.x = h0; ha.y = h1;
    __nv_bfloat162 hb; hb.x = h2; hb.y = h3;
    __nv_bfloat162 la; la.x = l0; la.y = l1;
    __nv_bfloat162 lb; lb.x = l2; lb.y = l3;
    *reinterpret_cast<__nv_bfloat162*>(row + k)           = ha;
    *reinterpret_cast<__nv_bfloat162*>(row + k + 2)       = hb;
    *reinterpret_cast<__nv_bfloat162*>(row + SEQ + k)     = la;
    *reinterpret_cast<__nv_bfloat162*>(row + SEQ + k + 2) = lb;
}

// ============================================================
// aten: out = probs @ v   (per batch 2048x1024, K=2048 split)
// ============================================================
__global__ void __launch_bounds__(256, 2) aten_mma_kernel(float* __restrict__ out)
{
    extern __shared__ char smem[];
    const int tid = threadIdx.x;
    const int wid = tid >> 5, lane = tid & 31;
    const int wm = wid & 3, wn = wid >> 2;
    const int b  = blockIdx.z;
    const int m0 = blockIdx.y * 128;
    const int n0 = blockIdx.x * 128;
    const uint32_t sbase = smem_u32(smem);

    GemmAcc g = {};
    gemm_split_mainloop(g, sbase,
                        g_a2 + (size_t)b * SEQ * KP2 + (size_t)m0 * KP2,
                        g_b2 + (size_t)b * DMODEL * KP2 + (size_t)n0 * KP2,
                        SEQ, KP2, SEQ / 64, tid, wm, wn, lane);

#pragma unroll
    for (int i = 0; i < 2; i++) {
        int q = m0 + wm * 32 + i * 16 + (lane >> 2);
#pragma unroll
        for (int j = 0; j < 8; j++) {
            int n = n0 + wn * 64 + j * 8 + (lane & 3) * 2;
            float2 lo = make_float2(g.a[i][j][0], g.a[i][j][1]);
            float2 hi = make_float2(g.a[i][j][2], g.a[i][j][3]);
            *reinterpret_cast<float2*>(out + ((size_t)q * BATCH + b) * DMODEL + n)       = lo;
            *reinterpret_cast<float2*>(out + ((size_t)(q + 8) * BATCH + b) * DMODEL + n) = hi;
        }
    }
}

// ============================================================
extern "C" void kernel_launch(void* const* d_in, const int* in_sizes, int n_in,
                              void* d_out, int out_size)
{
    const float* query = (const float*)d_in[0];
    const float* key   = (const float*)d_in[1];
    const float* value = (const float*)d_in[2];
    const float* Wq    = (const float*)d_in[3];
    const float* bq    = (const float*)d_in[4];
    const float* Wk    = (const float*)d_in[5];
    const float* bk    = (const float*)d_in[6];
    const float* Wv    = (const float*)d_in[7];
    const float* bv    = (const float*)d_in[8];

    float* out   = (float*)d_out;
    float* aten  = out;                                   // (S, B, D)
    float* probs = out + (size_t)SEQ * BATCH * DMODEL;    // (B, S, S)

    static int attr_set = 0;
    if (!attr_set) {
        cudaFuncSetAttribute(aten_mma_kernel,   cudaFuncAttributeMaxDynamicSharedMemorySize, GM_SMEM);
        cudaFuncSetAttribute(projv_mma_kernel,  cudaFuncAttributeMaxDynamicSharedMemorySize, GM_SMEM);
        cudaFuncSetAttribute(scores_mma_kernel, cudaFuncAttributeMaxDynamicSharedMemorySize, GM_SMEM);
        attr_set = 1;
    }

    // q/k projections (fp32 compute, split bf16 emit)
    {
        dim3 grid(MTOT / 64, 2);
        projqk_kernel<<<grid, 256>>>(query, Wq, bq, key, Wk, bk);
    }

    // v projection via split mma GEMM
    xvsplit_kernel<<<(MTOT * DMODEL / 4) / 256, 256>>>(value);
    {
        dim3 grid(DMODEL / 32, DMODEL / 32);
        wvsplit_kernel<<<grid, 256>>>(Wv);
    }
    {
        dim3 grid(DMODEL / 128, MTOT / 128);
        projv_mma_kernel<<<grid, 256, GM_SMEM>>>(bv);
    }

    // v split+transpose to bf16 for aten
    {
        dim3 grid(DMODEL / 32, SEQ / 32, BATCH);
        vsplit_kernel<<<grid, 256>>>();
    }

    // scores via split mma GEMM -> raw scaled scores in probs region
    {
        dim3 grid(SEQ / 128, SEQ / 128, BATCH);
        scores_mma_kernel<<<grid, 256, GM_SMEM>>>(probs);
    }

    // row softmax in place
    rowsoftmax_kernel<<<BATCH * SEQ, 256>>>(probs);

    // column sums (two stage) + in-place renorm (+ emit bf16 split of probs)
    {
        dim3 grid(SEQ / 256, BATCH, QCHUNK);
        colsum1_kernel<<<grid, 256>>>(probs);
    }
    colsum2_kernel<<<BATCH * SEQ / 256, 256>>>();
    {
        size_t total4 = (size_t)BATCH * SEQ * SEQ / 4;
        renorm_split_kernel<<<(unsigned)(total4 / 256), 256>>>(probs);
    }

    // aten = probs @ v  via split mma GEMM
    {
        dim3 grid(DMODEL / 128, SEQ / 128, BATCH);
        aten_mma_kernel<<<grid, 256, GM_SMEM>>>(aten);
    }
}

// round 16
// speedup vs baseline: 1.2269x; 1.0560x over previous
#include <cuda_runtime.h>
#include <cuda_bf16.h>
#include <cstdint>

#define SEQ    2048
#define BATCH  4
#define DMODEL 1024
#define DINT   64
#define MTOT   (SEQ * BATCH)   // 8192
#define KP2    (2 * SEQ)       // 4096: [hi|lo] rows for aten operands
#define KPV2   (2 * DMODEL)    // 2048: [hi|lo] rows for projv operands
#define KQ2    (2 * DINT)      // 128:  [hi|lo] rows for q/k operands
#define QCHUNK 16              // colsum partial chunks

// ---- scratch (device globals: allocation-free) ----
__device__ float g_v[BATCH * SEQ * DMODEL];
__device__ float g_colsum[BATCH * SEQ];
__device__ float g_cs_part[QCHUNK * BATCH * SEQ];
__device__ alignas(256) __nv_bfloat16 g_q2[(size_t)BATCH * SEQ * KQ2];     // q      [b][s][hi|lo]
__device__ alignas(256) __nv_bfloat16 g_k2[(size_t)BATCH * SEQ * KQ2];     // k      [b][s][hi|lo]
__device__ alignas(256) __nv_bfloat16 g_a2[(size_t)BATCH * SEQ * KP2];     // probs  [b][q][hi|lo]
__device__ alignas(256) __nv_bfloat16 g_b2[(size_t)BATCH * DMODEL * KP2];  // v^T    [b][n][hi|lo]
__device__ alignas(256) __nv_bfloat16 g_xv2[(size_t)MTOT * KPV2];          // value  [m][hi|lo]
__device__ alignas(256) __nv_bfloat16 g_wv2[(size_t)DMODEL * KPV2];        // Wv^T   [n][hi|lo]

// ================= baseline-ISA helpers =================
__device__ __forceinline__ uint32_t smem_u32(const void* p) {
    uint32_t a;
    asm("{ .reg .u64 t; cvta.to.shared.u64 t, %1; cvt.u32.u64 %0, t; }" : "=r"(a) : "l"(p));
    return a;
}
#define SMEM_SWIZZLE_128B(o) ((o) ^ (((o) >> 3) & 0x70))
#define CP_ASYNC16(dst, src) \
    asm volatile("cp.async.cg.shared.global [%0], [%1], 16;" :: "r"(dst), "l"(src) : "memory")
#define CP_COMMIT() asm volatile("cp.async.commit_group;" ::: "memory")
#define CP_WAIT(n)  asm volatile("cp.async.wait_group %0;" :: "n"(n) : "memory")
#define LDSM_X4(r0, r1, r2, r3, addr) \
    asm volatile("ldmatrix.sync.aligned.m8n8.x4.shared.b16 {%0,%1,%2,%3}, [%4];" \
        : "=r"(r0), "=r"(r1), "=r"(r2), "=r"(r3) : "r"(addr))
#define MMA16816(d, a0, a1, a2, a3, b0, b1) \
    asm volatile("mma.sync.aligned.m16n8k16.row.col.f32.bf16.bf16.f32 " \
        "{%0,%1,%2,%3}, {%4,%5,%6,%7}, {%8,%9}, {%0,%1,%2,%3};" \
        : "+f"((d)[0]), "+f"((d)[1]), "+f"((d)[2]), "+f"((d)[3]) \
        : "r"(a0), "r"(a1), "r"(a2), "r"(a3), "r"(b0), "r"(b1))

__device__ __forceinline__ void split2(float v, __nv_bfloat16& h, __nv_bfloat16& l) {
    h = __float2bfloat16(v);
    l = __float2bfloat16(v - __bfloat162float(h));
}

__global__ void noop_kernel() {}

// ============================================================
// q+k projections fused: X(8192,1024) @ W(1024,64) + bias
// Emits split bf16 rows [hi|lo] directly to g_q2 / g_k2.
// ============================================================
__global__ void projqk_kernel(const float* __restrict__ Q,
                              const float* __restrict__ Wq,
                              const float* __restrict__ bq,
                              const float* __restrict__ Kin,
                              const float* __restrict__ Wk,
                              const float* __restrict__ bk)
{
    __shared__ float As[16][64];
    __shared__ float Bs[16][64];
    const int tid = threadIdx.x;
    const int tx = tid & 15, ty = tid >> 4;
    const int m0 = blockIdx.x * 64;
    const int which = blockIdx.y;
    const float* X    = which ? Kin : Q;
    const float* W    = which ? Wk  : Wq;
    const float* bias = which ? bk  : bq;
    __nv_bfloat16* out = which ? g_k2 : g_q2;

    float acc[4][4] = {};

    for (int k0 = 0; k0 < DMODEL; k0 += 16) {
        {
            int row = tid >> 2;
            int kg  = (tid & 3) * 4;
            float4 v = *reinterpret_cast<const float4*>(&X[(size_t)(m0 + row) * DMODEL + k0 + kg]);
            As[kg + 0][row] = v.x; As[kg + 1][row] = v.y;
            As[kg + 2][row] = v.z; As[kg + 3][row] = v.w;
        }
        {
            int row = tid >> 4;
            int col = (tid & 15) * 4;
            *reinterpret_cast<float4*>(&Bs[row][col]) =
                *reinterpret_cast<const float4*>(&W[(size_t)(k0 + row) * DINT + col]);
        }
        __syncthreads();
#pragma unroll
        for (int kk = 0; kk < 16; kk++) {
            float a[4], b[4];
#pragma unroll
            for (int i = 0; i < 4; i++) a[i] = As[kk][ty * 4 + i];
#pragma unroll
            for (int j = 0; j < 4; j++) b[j] = Bs[kk][tx * 4 + j];
#pragma unroll
            for (int i = 0; i < 4; i++)
#pragma unroll
                for (int j = 0; j < 4; j++) acc[i][j] += a[i] * b[j];
        }
        __syncthreads();
    }

#pragma unroll
    for (int i = 0; i < 4; i++) {
        int m = m0 + ty * 4 + i;
        int s = m >> 2, b = m & 3;
        __nv_bfloat16* orow = &out[(size_t)(b * SEQ + s) * KQ2];
#pragma unroll
        for (int j = 0; j < 4; j++) {
            int n = tx * 4 + j;
            float v = acc[i][j] + bias[n];
            __nv_bfloat16 h, l;
            split2(v, h, l);
            orow[n]        = h;
            orow[DINT + n] = l;
        }
    }
}

// ============================================================
// value split: value[m][k] -> g_xv2[m][ hi | lo ]
// ============================================================
__global__ void xvsplit_kernel(const float* __restrict__ X)
{
    size_t i4 = ((size_t)blockIdx.x * 256 + threadIdx.x) * 4;
    int k = (int)(i4 & (DMODEL - 1));
    int m = (int)(i4 >> 10);
    float4 p = *reinterpret_cast<const float4*>(&X[i4]);
    __nv_bfloat16 h0, h1, h2, h3, l0, l1, l2, l3;
    split2(p.x, h0, l0); split2(p.y, h1, l1);
    split2(p.z, h2, l2); split2(p.w, h3, l3);
    __nv_bfloat16* row = g_xv2 + (size_t)m * KPV2;
    __nv_bfloat162 ha; ha.x = h0; ha.y = h1;
    __nv_bfloat162 hb; hb.x = h2; hb.y = h3;
    __nv_bfloat162 la; la.x = l0; la.y = l1;
    __nv_bfloat162 lb; lb.x = l2; lb.y = l3;
    *reinterpret_cast<__nv_bfloat162*>(row + k)              = ha;
    *reinterpret_cast<__nv_bfloat162*>(row + k + 2)          = hb;
    *reinterpret_cast<__nv_bfloat162*>(row + DMODEL + k)     = la;
    *reinterpret_cast<__nv_bfloat162*>(row + DMODEL + k + 2) = lb;
}

// ============================================================
// Wv split+transpose: W[k][n] -> g_wv2[n][ hi | lo ]
// ============================================================
__global__ void wvsplit_kernel(const float* __restrict__ W)
{
    __shared__ float t[32][33];
    const int tid = threadIdx.x;
    const int n0 = blockIdx.x * 32;
    const int k0 = blockIdx.y * 32;

#pragma unroll
    for (int r = 0; r < 4; r++) {
        int idx = tid + r * 256;
        int kl = idx >> 5, nl = idx & 31;
        t[kl][nl] = W[(size_t)(k0 + kl) * DMODEL + n0 + nl];
    }
    __syncthreads();

#pragma unroll
    for (int r = 0; r < 2; r++) {
        int idx = tid + r * 256;
        int nl = idx >> 4;
        int kp = (idx & 15) * 2;
        float v0 = t[kp][nl], v1 = t[kp + 1][nl];
        __nv_bfloat16 h0, h1, l0, l1;
        split2(v0, h0, l0); split2(v1, h1, l1);
        __nv_bfloat16* row = g_wv2 + (size_t)(n0 + nl) * KPV2;
        __nv_bfloat162 hh; hh.x = h0; hh.y = h1;
        __nv_bfloat162 ll; ll.x = l0; ll.y = l1;
        *reinterpret_cast<__nv_bfloat162*>(row + k0 + kp)          = hh;
        *reinterpret_cast<__nv_bfloat162*>(row + DMODEL + k0 + kp) = ll;
    }
}

// ============================================================
// shared GEMM core (round-15 config): 256 thr / 8 warps, warp tile
// 32x64, single-buffer 4x16KB, occ 2, three independent MMA sweeps.
// ============================================================
#define T_A_HI 0
#define T_A_LO 16384
#define T_B_HI 32768
#define T_B_LO 49152
#define GM_SMEM 65536

struct GemmAcc { float a[2][8][4]; };

__device__ __forceinline__ void gemm_split_mainloop(
    GemmAcc& g, uint32_t sbase,
    const __nv_bfloat16* Ag, const __nv_bfloat16* Bg,
    int kseg, int rowlen, int nchunk, int tid, int wm, int wn, int lane)
{
#pragma unroll 1
    for (int c = 0; c < nchunk; c++) {
        const int k0 = c * 64;
        if (c > 0) __syncthreads();
#pragma unroll
        for (int r = 0; r < 4; r++) {
            int idx = tid + r * 256;
            int row = idx >> 3, u = idx & 7;
            uint32_t off = SMEM_SWIZZLE_128B((uint32_t)(row * 128 + u * 16));
            const __nv_bfloat16* arow = Ag + (size_t)row * rowlen + k0 + u * 8;
            const __nv_bfloat16* brow = Bg + (size_t)row * rowlen + k0 + u * 8;
            CP_ASYNC16(sbase + T_A_HI + off, arow);
            CP_ASYNC16(sbase + T_A_LO + off, arow + kseg);
            CP_ASYNC16(sbase + T_B_HI + off, brow);
            CP_ASYNC16(sbase + T_B_LO + off, brow + kseg);
        }
        CP_COMMIT();
        CP_WAIT(0);
        __syncthreads();

#pragma unroll
        for (int kk = 0; kk < 4; kk++) {
            uint32_t af_h[8], af_l[8];
#pragma unroll
            for (int i = 0; i < 2; i++) {
                int row = wm * 32 + i * 16 + (lane & 15);
                uint32_t off = SMEM_SWIZZLE_128B(
                    (uint32_t)(row * 128 + kk * 32 + ((lane >> 4) & 1) * 16));
                LDSM_X4(af_h[i * 4 + 0], af_h[i * 4 + 1], af_h[i * 4 + 2], af_h[i * 4 + 3],
                        sbase + T_A_HI + off);
                LDSM_X4(af_l[i * 4 + 0], af_l[i * 4 + 1], af_l[i * 4 + 2], af_l[i * 4 + 3],
                        sbase + T_A_LO + off);
            }
            uint32_t bf[16];
#pragma unroll
            for (int j = 0; j < 4; j++) {
                int row = wn * 64 + j * 16 + ((lane >> 1) & 8) + (lane & 7);
                uint32_t off = SMEM_SWIZZLE_128B(
                    (uint32_t)(row * 128 + kk * 32 + ((lane >> 3) & 1) * 16));
                LDSM_X4(bf[j * 4 + 0], bf[j * 4 + 1], bf[j * 4 + 2], bf[j * 4 + 3],
                        sbase + T_B_HI + off);
            }
#pragma unroll
            for (int i = 0; i < 2; i++)
#pragma unroll
                for (int j = 0; j < 8; j++) {
                    int bidx = (j >> 1) * 4 + (j & 1) * 2;
                    MMA16816(g.a[i][j],
                             af_h[i * 4 + 0], af_h[i * 4 + 1], af_h[i * 4 + 2], af_h[i * 4 + 3],
                             bf[bidx], bf[bidx + 1]);
                }
#pragma unroll
            for (int i = 0; i < 2; i++)
#pragma unroll
                for (int j = 0; j < 8; j++) {
                    int bidx = (j >> 1) * 4 + (j & 1) * 2;
                    MMA16816(g.a[i][j],
                             af_l[i * 4 + 0], af_l[i * 4 + 1], af_l[i * 4 + 2], af_l[i * 4 + 3],
                             bf[bidx], bf[bidx + 1]);
                }
#pragma unroll
            for (int j = 0; j < 4; j++) {
                int row = wn * 64 + j * 16 + ((lane >> 1) & 8) + (lane & 7);
                uint32_t off = SMEM_SWIZZLE_128B(
                    (uint32_t)(row * 128 + kk * 32 + ((lane >> 3) & 1) * 16));
                LDSM_X4(bf[j * 4 + 0], bf[j * 4 + 1], bf[j * 4 + 2], bf[j * 4 + 3],
                        sbase + T_B_LO + off);
            }
#pragma unroll
            for (int i = 0; i < 2; i++)
#pragma unroll
                for (int j = 0; j < 8; j++) {
                    int bidx = (j >> 1) * 4 + (j & 1) * 2;
                    MMA16816(g.a[i][j],
                             af_h[i * 4 + 0], af_h[i * 4 + 1], af_h[i * 4 + 2], af_h[i * 4 + 3],
                             bf[bidx], bf[bidx + 1]);
                }
        }
    }
}

// ============================================================
// scores = q @ k^T * 0.125 via split mma (K'=64, 1 chunk)
// ============================================================
__global__ void __launch_bounds__(256, 2) scores_mma_kernel(float* __restrict__ probs)
{
    extern __shared__ char smem[];
    const int tid = threadIdx.x;
    const int wid = tid >> 5, lane = tid & 31;
    const int wm = wid & 3, wn = wid >> 2;
    const int b  = blockIdx.z;
    const int m0 = blockIdx.y * 128;
    const int n0 = blockIdx.x * 128;
    const uint32_t sbase = smem_u32(smem);

    GemmAcc g = {};
    gemm_split_mainloop(g, sbase,
                        g_q2 + (size_t)(b * SEQ + m0) * KQ2,
                        g_k2 + (size_t)(b * SEQ + n0) * KQ2,
                        DINT, KQ2, 1, tid, wm, wn, lane);

    float* C = probs + (size_t)b * SEQ * SEQ;
#pragma unroll
    for (int i = 0; i < 2; i++) {
        int row = m0 + wm * 32 + i * 16 + (lane >> 2);
#pragma unroll
        for (int j = 0; j < 8; j++) {
            int n = n0 + wn * 64 + j * 8 + (lane & 3) * 2;
            float2 lo = make_float2(g.a[i][j][0] * 0.125f, g.a[i][j][1] * 0.125f);
            float2 hi = make_float2(g.a[i][j][2] * 0.125f, g.a[i][j][3] * 0.125f);
            *reinterpret_cast<float2*>(C + (size_t)row * SEQ + n)       = lo;
            *reinterpret_cast<float2*>(C + (size_t)(row + 8) * SEQ + n) = hi;
        }
    }
}

// ============================================================
// projv: g_v = value @ Wv + bv   (M=8192, N=1024, K=1024 split)
// ============================================================
__global__ void __launch_bounds__(256, 2) projv_mma_kernel(const float* __restrict__ bias)
{
    extern __shared__ char smem[];
    const int tid = threadIdx.x;
    const int wid = tid >> 5, lane = tid & 31;
    const int wm = wid & 3, wn = wid >> 2;
    const int m0 = blockIdx.y * 128;
    const int n0 = blockIdx.x * 128;
    const uint32_t sbase = smem_u32(smem);

    GemmAcc g = {};
    gemm_split_mainloop(g, sbase,
                        g_xv2 + (size_t)m0 * KPV2,
                        g_wv2 + (size_t)n0 * KPV2,
                        DMODEL, KPV2, DMODEL / 64, tid, wm, wn, lane);

#pragma unroll
    for (int i = 0; i < 2; i++) {
        int m_a = m0 + wm * 32 + i * 16 + (lane >> 2);
        int m_b = m_a + 8;
        int sa = m_a >> 2, ba = m_a & 3;
        int sb = m_b >> 2, bb2 = m_b & 3;
#pragma unroll
        for (int j = 0; j < 8; j++) {
            int n = n0 + wn * 64 + j * 8 + (lane & 3) * 2;
            float2 bias2 = *reinterpret_cast<const float2*>(bias + n);
            float2 lo = make_float2(g.a[i][j][0] + bias2.x, g.a[i][j][1] + bias2.y);
            float2 hi = make_float2(g.a[i][j][2] + bias2.x, g.a[i][j][3] + bias2.y);
            *reinterpret_cast<float2*>(g_v + ((size_t)(ba * SEQ + sa)) * DMODEL + n)  = lo;
            *reinterpret_cast<float2*>(g_v + ((size_t)(bb2 * SEQ + sb)) * DMODEL + n) = hi;
        }
    }
}

// ============================================================
// v split+transpose: g_v[b][s][n] -> g_b2[b][n][ hi | lo ]
// ============================================================
__global__ void vsplit_kernel()
{
    __shared__ float t[32][33];
    const int tid = threadIdx.x;
    const int b  = blockIdx.z;
    const int n0 = blockIdx.x * 32;
    const int s0 = blockIdx.y * 32;

#pragma unroll
    for (int r = 0; r < 4; r++) {
        int idx = tid + r * 256;
        int sl = idx >> 5, nl = idx & 31;
        t[sl][nl] = g_v[((size_t)(b * SEQ + s0 + sl)) * DMODEL + n0 + nl];
    }
    __syncthreads();

#pragma unroll
    for (int r = 0; r < 2; r++) {
        int idx = tid + r * 256;
        int nl = idx >> 4;
        int sp = (idx & 15) * 2;
        float v0 = t[sp][nl], v1 = t[sp + 1][nl];
        __nv_bfloat16 h0, h1, l0, l1;
        split2(v0, h0, l0); split2(v1, h1, l1);
        __nv_bfloat16* row = g_b2 + ((size_t)(b * DMODEL + n0 + nl)) * KP2;
        __nv_bfloat162 hh; hh.x = h0; hh.y = h1;
        __nv_bfloat162 ll; ll.x = l0; ll.y = l1;
        *reinterpret_cast<__nv_bfloat162*>(row + s0 + sp)       = hh;
        *reinterpret_cast<__nv_bfloat162*>(row + SEQ + s0 + sp) = ll;
    }
}

// ============================================================
// row softmax in place
// ============================================================
__global__ void rowsoftmax_kernel(float* __restrict__ probs)
{
    const int tid = threadIdx.x;
    float* p = probs + (size_t)blockIdx.x * SEQ;

    __shared__ float red[8];

    float4 v0 = reinterpret_cast<float4*>(p)[tid];
    float4 v1 = reinterpret_cast<float4*>(p)[tid + 256];

    float mx = fmaxf(fmaxf(fmaxf(v0.x, v0.y), fmaxf(v0.z, v0.w)),
                     fmaxf(fmaxf(v1.x, v1.y), fmaxf(v1.z, v1.w)));
#pragma unroll
    for (int o = 16; o > 0; o >>= 1)
        mx = fmaxf(mx, __shfl_xor_sync(0xffffffffu, mx, o));
    if ((tid & 31) == 0) red[tid >> 5] = mx;
    __syncthreads();
    {
        float m = red[tid & 7];
#pragma unroll
        for (int o = 4; o > 0; o >>= 1)
            m = fmaxf(m, __shfl_xor_sync(0xffffffffu, m, o));
        mx = m;
    }

    v0.x = __expf(v0.x - mx); v0.y = __expf(v0.y - mx);
    v0.z = __expf(v0.z - mx); v0.w = __expf(v0.w - mx);
    v1.x = __expf(v1.x - mx); v1.y = __expf(v1.y - mx);
    v1.z = __expf(v1.z - mx); v1.w = __expf(v1.w - mx);

    float sum = v0.x + v0.y + v0.z + v0.w + v1.x + v1.y + v1.z + v1.w;
#pragma unroll
    for (int o = 16; o > 0; o >>= 1)
        sum += __shfl_xor_sync(0xffffffffu, sum, o);
    __syncthreads();
    if ((tid & 31) == 0) red[tid >> 5] = sum;
    __syncthreads();
    {
        float s = red[tid & 7];
#pragma unroll
        for (int o = 4; o > 0; o >>= 1)
            s += __shfl_xor_sync(0xffffffffu, s, o);
        sum = s;
    }
    float inv = 1.0f / sum;

    v0.x *= inv; v0.y *= inv; v0.z *= inv; v0.w *= inv;
    v1.x *= inv; v1.y *= inv; v1.z *= inv; v1.w *= inv;
    reinterpret_cast<float4*>(p)[tid]       = v0;
    reinterpret_cast<float4*>(p)[tid + 256] = v1;
}

// ============================================================
// column sums (two stage)
// ============================================================
__global__ void colsum1_kernel(const float* __restrict__ probs)
{
    const int k  = blockIdx.x * 256 + threadIdx.x;
    const int b  = blockIdx.y;
    const int qc = blockIdx.z;
    const float* p = probs + (size_t)b * SEQ * SEQ + (size_t)qc * 128 * SEQ + k;
    float s = 0.f;
#pragma unroll 4
    for (int q = 0; q < 128; q++) s += p[(size_t)q * SEQ];
    g_cs_part[(size_t)(qc * BATCH + b) * SEQ + k] = s;
}

__global__ void colsum2_kernel()
{
    const int i = blockIdx.x * 256 + threadIdx.x;
    float s = 0.f;
#pragma unroll
    for (int c = 0; c < QCHUNK; c++) s += g_cs_part[(size_t)c * BATCH * SEQ + i];
    g_colsum[i] = s;
}

// ============================================================
// renorm in place + emit bf16 split A2 = [hi | lo]
// ============================================================
__global__ void renorm_split_kernel(float* __restrict__ probs)
{
    size_t i4 = ((size_t)blockIdx.x * 256 + threadIdx.x) * 4;
    int k = (int)(i4 & (SEQ - 1));
    int q = (int)((i4 >> 11) & (SEQ - 1));
    int b = (int)(i4 >> 22);
    float4 p = *reinterpret_cast<float4*>(&probs[i4]);
    const float4 c = *reinterpret_cast<const float4*>(&g_colsum[b * SEQ + k]);
    p.x /= (1e-9f + c.x);
    p.y /= (1e-9f + c.y);
    p.z /= (1e-9f + c.z);
    p.w /= (1e-9f + c.w);
    *reinterpret_cast<float4*>(&probs[i4]) = p;

    __nv_bfloat16 h0, h1, h2, h3, l0, l1, l2, l3;
    split2(p.x, h0, l0); split2(p.y, h1, l1);
    split2(p.z, h2, l2); split2(p.w, h3, l3);

    __nv_bfloat16* row = g_a2 + ((size_t)(b * SEQ + q)) * KP2;
    __nv_bfloat162 ha; ha.x = h0; ha.y = h1;
    __nv_bfloat162 hb; hb.x = h2; hb.y = h3;
    __nv_bfloat162 la; la.x = l0; la.y = l1;
    __nv_bfloat162 lb; lb.x = l2; lb.y = l3;
    *reinterpret_cast<__nv_bfloat162*>(row + k)           = ha;
    *reinterpret_cast<__nv_bfloat162*>(row + k + 2)       = hb;
    *reinterpret_cast<__nv_bfloat162*>(row + SEQ + k)     = la;
    *reinterpret_cast<__nv_bfloat162*>(row + SEQ + k + 2) = lb;
}

// ============================================================
// aten: out = probs @ v   (per batch 2048x1024, K=2048 split)
// ============================================================
__global__ void __launch_bounds__(256, 2) aten_mma_kernel(float* __restrict__ out)
{
    extern __shared__ char smem[];
    const int tid = threadIdx.x;
    const int wid = tid >> 5, lane = tid & 31;
    const int wm = wid & 3, wn = wid >> 2;
    const int b  = blockIdx.z;
    const int m0 = blockIdx.y * 128;
    const int n0 = blockIdx.x * 128;
    const uint32_t sbase = smem_u32(smem);

    GemmAcc g = {};
    gemm_split_mainloop(g, sbase,
                        g_a2 + (size_t)b * SEQ * KP2 + (size_t)m0 * KP2,
                        g_b2 + (size_t)b * DMODEL * KP2 + (size_t)n0 * KP2,
                        SEQ, KP2, SEQ / 64, tid, wm, wn, lane);

#pragma unroll
    for (int i = 0; i < 2; i++) {
        int q = m0 + wm * 32 + i * 16 + (lane >> 2);
#pragma unroll
        for (int j = 0; j < 8; j++) {
            int n = n0 + wn * 64 + j * 8 + (lane & 3) * 2;
            float2 lo = make_float2(g.a[i][j][0], g.a[i][j][1]);
            float2 hi = make_float2(g.a[i][j][2], g.a[i][j][3]);
            *reinterpret_cast<float2*>(out + ((size_t)q * BATCH + b) * DMODEL + n)       = lo;
            *reinterpret_cast<float2*>(out + ((size_t)(q + 8) * BATCH + b) * DMODEL + n) = hi;
        }
    }
}

// ============================================================
// stream/event setup at program init (outside harness checkpoints
// and outside graph capture; no device-memory allocation APIs used)
// ============================================================
struct StreamInit {
    cudaStream_t s1 = nullptr, s2 = nullptr;
    cudaEvent_t  e0 = nullptr, e1 = nullptr, e2 = nullptr;
    StreamInit() {
        cudaStreamCreateWithFlags(&s1, cudaStreamNonBlocking);
        cudaStreamCreateWithFlags(&s2, cudaStreamNonBlocking);
        cudaEventCreateWithFlags(&e0, cudaEventDisableTiming);
        cudaEventCreateWithFlags(&e1, cudaEventDisableTiming);
        cudaEventCreateWithFlags(&e2, cudaEventDisableTiming);
        cudaFuncSetAttribute(aten_mma_kernel,   cudaFuncAttributeMaxDynamicSharedMemorySize, GM_SMEM);
        cudaFuncSetAttribute(projv_mma_kernel,  cudaFuncAttributeMaxDynamicSharedMemorySize, GM_SMEM);
        cudaFuncSetAttribute(scores_mma_kernel, cudaFuncAttributeMaxDynamicSharedMemorySize, GM_SMEM);
        // warm up stream resources so no lazy allocation happens later
        noop_kernel<<<1, 32>>>();
        noop_kernel<<<1, 32, 0, s1>>>();
        noop_kernel<<<1, 32, 0, s2>>>();
        cudaDeviceSynchronize();
    }
};
static StreamInit g_si;

// ============================================================
extern "C" void kernel_launch(void* const* d_in, const int* in_sizes, int n_in,
                              void* d_out, int out_size)
{
    const float* query = (const float*)d_in[0];
    const float* key   = (const float*)d_in[1];
    const float* value = (const float*)d_in[2];
    const float* Wq    = (const float*)d_in[3];
    const float* bq    = (const float*)d_in[4];
    const float* Wk    = (const float*)d_in[5];
    const float* bk    = (const float*)d_in[6];
    const float* Wv    = (const float*)d_in[7];
    const float* bv    = (const float*)d_in[8];

    float* out   = (float*)d_out;
    float* aten  = out;                                   // (S, B, D)
    float* probs = out + (size_t)SEQ * BATCH * DMODEL;    // (B, S, S)

    cudaStream_t s1 = g_si.s1, s2 = g_si.s2;

    // ---- fork ----
    cudaEventRecord(g_si.e0, 0);
    cudaStreamWaitEvent(s1, g_si.e0, 0);
    cudaStreamWaitEvent(s2, g_si.e0, 0);

    // ===== chain A (s1): q/k -> scores -> softmax -> colsum -> renorm =====
    {
        dim3 grid(MTOT / 64, 2);
        projqk_kernel<<<grid, 256, 0, s1>>>(query, Wq, bq, key, Wk, bk);
    }
    {
        dim3 grid(SEQ / 128, SEQ / 128, BATCH);
        scores_mma_kernel<<<grid, 256, GM_SMEM, s1>>>(probs);
    }
    rowsoftmax_kernel<<<BATCH * SEQ, 256, 0, s1>>>(probs);
    {
        dim3 grid(SEQ / 256, BATCH, QCHUNK);
        colsum1_kernel<<<grid, 256, 0, s1>>>(probs);
    }
    colsum2_kernel<<<BATCH * SEQ / 256, 256, 0, s1>>>();
    {
        size_t total4 = (size_t)BATCH * SEQ * SEQ / 4;
        renorm_split_kernel<<<(unsigned)(total4 / 256), 256, 0, s1>>>(probs);
    }

    // ===== chain B (s2): value split -> Wv split -> projv -> vsplit =====
    xvsplit_kernel<<<(MTOT * DMODEL / 4) / 256, 256, 0, s2>>>(value);
    {
        dim3 grid(DMODEL / 32, DMODEL / 32);
        wvsplit_kernel<<<grid, 256, 0, s2>>>(Wv);
    }
    {
        dim3 grid(DMODEL / 128, MTOT / 128);
        projv_mma_kernel<<<grid, 256, GM_SMEM, s2>>>(bv);
    }
    {
        dim3 grid(DMODEL / 32, SEQ / 32, BATCH);
        vsplit_kernel<<<grid, 256, 0, s2>>>();
    }

    // ---- join ----
    cudaEventRecord(g_si.e1, s1);
    cudaEventRecord(g_si.e2, s2);
    cudaStreamWaitEvent(0, g_si.e1, 0);
    cudaStreamWaitEvent(0, g_si.e2, 0);

    // aten = probs @ v  via split mma GEMM (stream 0)
    {
        dim3 grid(DMODEL / 128, SEQ / 128, BATCH);
        aten_mma_kernel<<<grid, 256, GM_SMEM>>>(aten);
    }
}

// round 17
// speedup vs baseline: 1.2714x; 1.0362x over previous
#include <cuda_runtime.h>
#include <cuda_bf16.h>
#include <cstdint>

#define SEQ    2048
#define BATCH  4
#define DMODEL 1024
#define DINT   64
#define MTOT   (SEQ * BATCH)   // 8192
#define KP2    (2 * SEQ)       // 4096: [hi|lo] rows for aten operands
#define KPV2   (2 * DMODEL)    // 2048: [hi|lo] rows for projv operands
#define KQ2    (2 * DINT)      // 128:  [hi|lo] rows for q/k operands
#define QCHUNK 16              // colsum partial chunks
#define PKC    4               // projqk split-K chunks

// ---- scratch (device globals: allocation-free) ----
__device__ float g_v[BATCH * SEQ * DMODEL];
__device__ float g_colsum[BATCH * SEQ];
__device__ float g_cs_part[QCHUNK * BATCH * SEQ];
__device__ float g_qk_part[(size_t)2 * PKC * MTOT * DINT];                 // partial q/k sums
__device__ alignas(256) __nv_bfloat16 g_q2[(size_t)BATCH * SEQ * KQ2];     // q      [b][s][hi|lo]
__device__ alignas(256) __nv_bfloat16 g_k2[(size_t)BATCH * SEQ * KQ2];     // k      [b][s][hi|lo]
__device__ alignas(256) __nv_bfloat16 g_a2[(size_t)BATCH * SEQ * KP2];     // probs  [b][q][hi|lo]
__device__ alignas(256) __nv_bfloat16 g_b2[(size_t)BATCH * DMODEL * KP2];  // v^T    [b][n][hi|lo]
__device__ alignas(256) __nv_bfloat16 g_xv2[(size_t)MTOT * KPV2];          // value  [m][hi|lo]
__device__ alignas(256) __nv_bfloat16 g_wv2[(size_t)DMODEL * KPV2];        // Wv^T   [n][hi|lo]

// ================= baseline-ISA helpers =================
__device__ __forceinline__ uint32_t smem_u32(const void* p) {
    uint32_t a;
    asm("{ .reg .u64 t; cvta.to.shared.u64 t, %1; cvt.u32.u64 %0, t; }" : "=r"(a) : "l"(p));
    return a;
}
#define SMEM_SWIZZLE_128B(o) ((o) ^ (((o) >> 3) & 0x70))
#define CP_ASYNC16(dst, src) \
    asm volatile("cp.async.cg.shared.global [%0], [%1], 16;" :: "r"(dst), "l"(src) : "memory")
#define CP_COMMIT() asm volatile("cp.async.commit_group;" ::: "memory")
#define CP_WAIT(n)  asm volatile("cp.async.wait_group %0;" :: "n"(n) : "memory")
#define LDSM_X4(r0, r1, r2, r3, addr) \
    asm volatile("ldmatrix.sync.aligned.m8n8.x4.shared.b16 {%0,%1,%2,%3}, [%4];" \
        : "=r"(r0), "=r"(r1), "=r"(r2), "=r"(r3) : "r"(addr))
#define MMA16816(d, a0, a1, a2, a3, b0, b1) \
    asm volatile("mma.sync.aligned.m16n8k16.row.col.f32.bf16.bf16.f32 " \
        "{%0,%1,%2,%3}, {%4,%5,%6,%7}, {%8,%9}, {%0,%1,%2,%3};" \
        : "+f"((d)[0]), "+f"((d)[1]), "+f"((d)[2]), "+f"((d)[3]) \
        : "r"(a0), "r"(a1), "r"(a2), "r"(a3), "r"(b0), "r"(b1))

__device__ __forceinline__ void split2(float v, __nv_bfloat16& h, __nv_bfloat16& l) {
    h = __float2bfloat16(v);
    l = __float2bfloat16(v - __bfloat162float(h));
}

__global__ void noop_kernel() {}

// ============================================================
// projqk split-K partial: X(8192,1024[kc-chunk]) @ W(256,64)
// grid (M/64, PKC, 2). Plain stores to g_qk_part.
// ============================================================
__global__ void projqk_partial_kernel(const float* __restrict__ Q,
                                      const float* __restrict__ Kin,
                                      const float* __restrict__ Wq,
                                      const float* __restrict__ Wk)
{
    __shared__ float As[16][64];
    __shared__ float Bs[16][64];
    const int tid = threadIdx.x;
    const int tx = tid & 15, ty = tid >> 4;
    const int m0 = blockIdx.x * 64;
    const int kc = blockIdx.y;
    const int which = blockIdx.z;
    const float* X = which ? Kin : Q;
    const float* W = which ? Wk  : Wq;

    float acc[4][4] = {};
    const int kbase = kc * (DMODEL / PKC);

    for (int k0 = kbase; k0 < kbase + DMODEL / PKC; k0 += 16) {
        {
            int row = tid >> 2;
            int kg  = (tid & 3) * 4;
            float4 v = *reinterpret_cast<const float4*>(&X[(size_t)(m0 + row) * DMODEL + k0 + kg]);
            As[kg + 0][row] = v.x; As[kg + 1][row] = v.y;
            As[kg + 2][row] = v.z; As[kg + 3][row] = v.w;
        }
        {
            int row = tid >> 4;
            int col = (tid & 15) * 4;
            *reinterpret_cast<float4*>(&Bs[row][col]) =
                *reinterpret_cast<const float4*>(&W[(size_t)(k0 + row) * DINT + col]);
        }
        __syncthreads();
#pragma unroll
        for (int kk = 0; kk < 16; kk++) {
            float a[4], b[4];
#pragma unroll
            for (int i = 0; i < 4; i++) a[i] = As[kk][ty * 4 + i];
#pragma unroll
            for (int j = 0; j < 4; j++) b[j] = Bs[kk][tx * 4 + j];
#pragma unroll
            for (int i = 0; i < 4; i++)
#pragma unroll
                for (int j = 0; j < 4; j++) acc[i][j] += a[i] * b[j];
        }
        __syncthreads();
    }

    float* part = g_qk_part + ((size_t)(kc * 2 + which)) * MTOT * DINT;
#pragma unroll
    for (int i = 0; i < 4; i++) {
        int m = m0 + ty * 4 + i;
        float4 v = make_float4(acc[i][0], acc[i][1], acc[i][2], acc[i][3]);
        *reinterpret_cast<float4*>(&part[(size_t)m * DINT + tx * 4]) = v;
    }
}

// ============================================================
// qk emit: sum PKC partials + bias, split2, write g_q2/g_k2
// ============================================================
__global__ void qkemit_kernel(const float* __restrict__ bq,
                              const float* __restrict__ bk)
{
    int gid = blockIdx.x * 256 + threadIdx.x;        // over 2*8192*16 quad groups
    int n4 = (gid & 15) * 4;
    int m  = (gid >> 4) & (MTOT - 1);
    int which = gid >> 17;

    float4 s = make_float4(0.f, 0.f, 0.f, 0.f);
#pragma unroll
    for (int c = 0; c < PKC; c++) {
        const float4 p = *reinterpret_cast<const float4*>(
            &g_qk_part[((size_t)(c * 2 + which)) * MTOT * DINT + (size_t)m * DINT + n4]);
        s.x += p.x; s.y += p.y; s.z += p.z; s.w += p.w;
    }
    const float* bias = which ? bk : bq;
    const float4 bi = *reinterpret_cast<const float4*>(bias + n4);
    s.x += bi.x; s.y += bi.y; s.z += bi.z; s.w += bi.w;

    int sq = m >> 2, b = m & 3;
    __nv_bfloat16* orow = (which ? g_k2 : g_q2) + (size_t)(b * SEQ + sq) * KQ2;
    __nv_bfloat16 h0, h1, h2, h3, l0, l1, l2, l3;
    split2(s.x, h0, l0); split2(s.y, h1, l1);
    split2(s.z, h2, l2); split2(s.w, h3, l3);
    __nv_bfloat162 ha; ha.x = h0; ha.y = h1;
    __nv_bfloat162 hb; hb.x = h2; hb.y = h3;
    __nv_bfloat162 la; la.x = l0; la.y = l1;
    __nv_bfloat162 lb; lb.x = l2; lb.y = l3;
    *reinterpret_cast<__nv_bfloat162*>(orow + n4)            = ha;
    *reinterpret_cast<__nv_bfloat162*>(orow + n4 + 2)        = hb;
    *reinterpret_cast<__nv_bfloat162*>(orow + DINT + n4)     = la;
    *reinterpret_cast<__nv_bfloat162*>(orow + DINT + n4 + 2) = lb;
}

// ============================================================
// value split: value[m][k] -> g_xv2[m][ hi | lo ]
// ============================================================
__global__ void xvsplit_kernel(const float* __restrict__ X)
{
    size_t i4 = ((size_t)blockIdx.x * 256 + threadIdx.x) * 4;
    int k = (int)(i4 & (DMODEL - 1));
    int m = (int)(i4 >> 10);
    float4 p = *reinterpret_cast<const float4*>(&X[i4]);
    __nv_bfloat16 h0, h1, h2, h3, l0, l1, l2, l3;
    split2(p.x, h0, l0); split2(p.y, h1, l1);
    split2(p.z, h2, l2); split2(p.w, h3, l3);
    __nv_bfloat16* row = g_xv2 + (size_t)m * KPV2;
    __nv_bfloat162 ha; ha.x = h0; ha.y = h1;
    __nv_bfloat162 hb; hb.x = h2; hb.y = h3;
    __nv_bfloat162 la; la.x = l0; la.y = l1;
    __nv_bfloat162 lb; lb.x = l2; lb.y = l3;
    *reinterpret_cast<__nv_bfloat162*>(row + k)              = ha;
    *reinterpret_cast<__nv_bfloat162*>(row + k + 2)          = hb;
    *reinterpret_cast<__nv_bfloat162*>(row + DMODEL + k)     = la;
    *reinterpret_cast<__nv_bfloat162*>(row + DMODEL + k + 2) = lb;
}

// ============================================================
// Wv split+transpose: W[k][n] -> g_wv2[n][ hi | lo ]
// ============================================================
__global__ void wvsplit_kernel(const float* __restrict__ W)
{
    __shared__ float t[32][33];
    const int tid = threadIdx.x;
    const int n0 = blockIdx.x * 32;
    const int k0 = blockIdx.y * 32;

#pragma unroll
    for (int r = 0; r < 4; r++) {
        int idx = tid + r * 256;
        int kl = idx >> 5, nl = idx & 31;
        t[kl][nl] = W[(size_t)(k0 + kl) * DMODEL + n0 + nl];
    }
    __syncthreads();

#pragma unroll
    for (int r = 0; r < 2; r++) {
        int idx = tid + r * 256;
        int nl = idx >> 4;
        int kp = (idx & 15) * 2;
        float v0 = t[kp][nl], v1 = t[kp + 1][nl];
        __nv_bfloat16 h0, h1, l0, l1;
        split2(v0, h0, l0); split2(v1, h1, l1);
        __nv_bfloat16* row = g_wv2 + (size_t)(n0 + nl) * KPV2;
        __nv_bfloat162 hh; hh.x = h0; hh.y = h1;
        __nv_bfloat162 ll; ll.x = l0; ll.y = l1;
        *reinterpret_cast<__nv_bfloat162*>(row + k0 + kp)          = hh;
        *reinterpret_cast<__nv_bfloat162*>(row + DMODEL + k0 + kp) = ll;
    }
}

// ============================================================
// shared GEMM core (round-15 config)
// ============================================================
#define T_A_HI 0
#define T_A_LO 16384
#define T_B_HI 32768
#define T_B_LO 49152
#define GM_SMEM 65536

struct GemmAcc { float a[2][8][4]; };

__device__ __forceinline__ void gemm_split_mainloop(
    GemmAcc& g, uint32_t sbase,
    const __nv_bfloat16* Ag, const __nv_bfloat16* Bg,
    int kseg, int rowlen, int nchunk, int tid, int wm, int wn, int lane)
{
#pragma unroll 1
    for (int c = 0; c < nchunk; c++) {
        const int k0 = c * 64;
        if (c > 0) __syncthreads();
#pragma unroll
        for (int r = 0; r < 4; r++) {
            int idx = tid + r * 256;
            int row = idx >> 3, u = idx & 7;
            uint32_t off = SMEM_SWIZZLE_128B((uint32_t)(row * 128 + u * 16));
            const __nv_bfloat16* arow = Ag + (size_t)row * rowlen + k0 + u * 8;
            const __nv_bfloat16* brow = Bg + (size_t)row * rowlen + k0 + u * 8;
            CP_ASYNC16(sbase + T_A_HI + off, arow);
            CP_ASYNC16(sbase + T_A_LO + off, arow + kseg);
            CP_ASYNC16(sbase + T_B_HI + off, brow);
            CP_ASYNC16(sbase + T_B_LO + off, brow + kseg);
        }
        CP_COMMIT();
        CP_WAIT(0);
        __syncthreads();

#pragma unroll
        for (int kk = 0; kk < 4; kk++) {
            uint32_t af_h[8], af_l[8];
#pragma unroll
            for (int i = 0; i < 2; i++) {
                int row = wm * 32 + i * 16 + (lane & 15);
                uint32_t off = SMEM_SWIZZLE_128B(
                    (uint32_t)(row * 128 + kk * 32 + ((lane >> 4) & 1) * 16));
                LDSM_X4(af_h[i * 4 + 0], af_h[i * 4 + 1], af_h[i * 4 + 2], af_h[i * 4 + 3],
                        sbase + T_A_HI + off);
                LDSM_X4(af_l[i * 4 + 0], af_l[i * 4 + 1], af_l[i * 4 + 2], af_l[i * 4 + 3],
                        sbase + T_A_LO + off);
            }
            uint32_t bf[16];
#pragma unroll
            for (int j = 0; j < 4; j++) {
                int row = wn * 64 + j * 16 + ((lane >> 1) & 8) + (lane & 7);
                uint32_t off = SMEM_SWIZZLE_128B(
                    (uint32_t)(row * 128 + kk * 32 + ((lane >> 3) & 1) * 16));
                LDSM_X4(bf[j * 4 + 0], bf[j * 4 + 1], bf[j * 4 + 2], bf[j * 4 + 3],
                        sbase + T_B_HI + off);
            }
#pragma unroll
            for (int i = 0; i < 2; i++)
#pragma unroll
                for (int j = 0; j < 8; j++) {
                    int bidx = (j >> 1) * 4 + (j & 1) * 2;
                    MMA16816(g.a[i][j],
                             af_h[i * 4 + 0], af_h[i * 4 + 1], af_h[i * 4 + 2], af_h[i * 4 + 3],
                             bf[bidx], bf[bidx + 1]);
                }
#pragma unroll
            for (int i = 0; i < 2; i++)
#pragma unroll
                for (int j = 0; j < 8; j++) {
                    int bidx = (j >> 1) * 4 + (j & 1) * 2;
                    MMA16816(g.a[i][j],
                             af_l[i * 4 + 0], af_l[i * 4 + 1], af_l[i * 4 + 2], af_l[i * 4 + 3],
                             bf[bidx], bf[bidx + 1]);
                }
#pragma unroll
            for (int j = 0; j < 4; j++) {
                int row = wn * 64 + j * 16 + ((lane >> 1) & 8) + (lane & 7);
                uint32_t off = SMEM_SWIZZLE_128B(
                    (uint32_t)(row * 128 + kk * 32 + ((lane >> 3) & 1) * 16));
                LDSM_X4(bf[j * 4 + 0], bf[j * 4 + 1], bf[j * 4 + 2], bf[j * 4 + 3],
                        sbase + T_B_LO + off);
            }
#pragma unroll
            for (int i = 0; i < 2; i++)
#pragma unroll
                for (int j = 0; j < 8; j++) {
                    int bidx = (j >> 1) * 4 + (j & 1) * 2;
                    MMA16816(g.a[i][j],
                             af_h[i * 4 + 0], af_h[i * 4 + 1], af_h[i * 4 + 2], af_h[i * 4 + 3],
                             bf[bidx], bf[bidx + 1]);
                }
        }
    }
}

// ============================================================
// scores = q @ k^T * 0.125 via split mma (K'=64, 1 chunk)
// ============================================================
__global__ void __launch_bounds__(256, 2) scores_mma_kernel(float* __restrict__ probs)
{
    extern __shared__ char smem[];
    const int tid = threadIdx.x;
    const int wid = tid >> 5, lane = tid & 31;
    const int wm = wid & 3, wn = wid >> 2;
    const int b  = blockIdx.z;
    const int m0 = blockIdx.y * 128;
    const int n0 = blockIdx.x * 128;
    const uint32_t sbase = smem_u32(smem);

    GemmAcc g = {};
    gemm_split_mainloop(g, sbase,
                        g_q2 + (size_t)(b * SEQ + m0) * KQ2,
                        g_k2 + (size_t)(b * SEQ + n0) * KQ2,
                        DINT, KQ2, 1, tid, wm, wn, lane);

    float* C = probs + (size_t)b * SEQ * SEQ;
#pragma unroll
    for (int i = 0; i < 2; i++) {
        int row = m0 + wm * 32 + i * 16 + (lane >> 2);
#pragma unroll
        for (int j = 0; j < 8; j++) {
            int n = n0 + wn * 64 + j * 8 + (lane & 3) * 2;
            float2 lo = make_float2(g.a[i][j][0] * 0.125f, g.a[i][j][1] * 0.125f);
            float2 hi = make_float2(g.a[i][j][2] * 0.125f, g.a[i][j][3] * 0.125f);
            *reinterpret_cast<float2*>(C + (size_t)row * SEQ + n)       = lo;
            *reinterpret_cast<float2*>(C + (size_t)(row + 8) * SEQ + n) = hi;
        }
    }
}

// ============================================================
// projv: g_v = value @ Wv + bv   (M=8192, N=1024, K=1024 split)
// ============================================================
__global__ void __launch_bounds__(256, 2) projv_mma_kernel(const float* __restrict__ bias)
{
    extern __shared__ char smem[];
    const int tid = threadIdx.x;
    const int wid = tid >> 5, lane = tid & 31;
    const int wm = wid & 3, wn = wid >> 2;
    const int m0 = blockIdx.y * 128;
    const int n0 = blockIdx.x * 128;
    const uint32_t sbase = smem_u32(smem);

    GemmAcc g = {};
    gemm_split_mainloop(g, sbase,
                        g_xv2 + (size_t)m0 * KPV2,
                        g_wv2 + (size_t)n0 * KPV2,
                        DMODEL, KPV2, DMODEL / 64, tid, wm, wn, lane);

#pragma unroll
    for (int i = 0; i < 2; i++) {
        int m_a = m0 + wm * 32 + i * 16 + (lane >> 2);
        int m_b = m_a + 8;
        int sa = m_a >> 2, ba = m_a & 3;
        int sb = m_b >> 2, bb2 = m_b & 3;
#pragma unroll
        for (int j = 0; j < 8; j++) {
            int n = n0 + wn * 64 + j * 8 + (lane & 3) * 2;
            float2 bias2 = *reinterpret_cast<const float2*>(bias + n);
            float2 lo = make_float2(g.a[i][j][0] + bias2.x, g.a[i][j][1] + bias2.y);
            float2 hi = make_float2(g.a[i][j][2] + bias2.x, g.a[i][j][3] + bias2.y);
            *reinterpret_cast<float2*>(g_v + ((size_t)(ba * SEQ + sa)) * DMODEL + n)  = lo;
            *reinterpret_cast<float2*>(g_v + ((size_t)(bb2 * SEQ + sb)) * DMODEL + n) = hi;
        }
    }
}

// ============================================================
// v split+transpose: g_v[b][s][n] -> g_b2[b][n][ hi | lo ]
// ============================================================
__global__ void vsplit_kernel()
{
    __shared__ float t[32][33];
    const int tid = threadIdx.x;
    const int b  = blockIdx.z;
    const int n0 = blockIdx.x * 32;
    const int s0 = blockIdx.y * 32;

#pragma unroll
    for (int r = 0; r < 4; r++) {
        int idx = tid + r * 256;
        int sl = idx >> 5, nl = idx & 31;
        t[sl][nl] = g_v[((size_t)(b * SEQ + s0 + sl)) * DMODEL + n0 + nl];
    }
    __syncthreads();

#pragma unroll
    for (int r = 0; r < 2; r++) {
        int idx = tid + r * 256;
        int nl = idx >> 4;
        int sp = (idx & 15) * 2;
        float v0 = t[sp][nl], v1 = t[sp + 1][nl];
        __nv_bfloat16 h0, h1, l0, l1;
        split2(v0, h0, l0); split2(v1, h1, l1);
        __nv_bfloat16* row = g_b2 + ((size_t)(b * DMODEL + n0 + nl)) * KP2;
        __nv_bfloat162 hh; hh.x = h0; hh.y = h1;
        __nv_bfloat162 ll; ll.x = l0; ll.y = l1;
        *reinterpret_cast<__nv_bfloat162*>(row + s0 + sp)       = hh;
        *reinterpret_cast<__nv_bfloat162*>(row + SEQ + s0 + sp) = ll;
    }
}

// ============================================================
// row softmax in place
// ============================================================
__global__ void rowsoftmax_kernel(float* __restrict__ probs)
{
    const int tid = threadIdx.x;
    float* p = probs + (size_t)blockIdx.x * SEQ;

    __shared__ float red[8];

    float4 v0 = reinterpret_cast<float4*>(p)[tid];
    float4 v1 = reinterpret_cast<float4*>(p)[tid + 256];

    float mx = fmaxf(fmaxf(fmaxf(v0.x, v0.y), fmaxf(v0.z, v0.w)),
                     fmaxf(fmaxf(v1.x, v1.y), fmaxf(v1.z, v1.w)));
#pragma unroll
    for (int o = 16; o > 0; o >>= 1)
        mx = fmaxf(mx, __shfl_xor_sync(0xffffffffu, mx, o));
    if ((tid & 31) == 0) red[tid >> 5] = mx;
    __syncthreads();
    {
        float m = red[tid & 7];
#pragma unroll
        for (int o = 4; o > 0; o >>= 1)
            m = fmaxf(m, __shfl_xor_sync(0xffffffffu, m, o));
        mx = m;
    }

    v0.x = __expf(v0.x - mx); v0.y = __expf(v0.y - mx);
    v0.z = __expf(v0.z - mx); v0.w = __expf(v0.w - mx);
    v1.x = __expf(v1.x - mx); v1.y = __expf(v1.y - mx);
    v1.z = __expf(v1.z - mx); v1.w = __expf(v1.w - mx);

    float sum = v0.x + v0.y + v0.z + v0.w + v1.x + v1.y + v1.z + v1.w;
#pragma unroll
    for (int o = 16; o > 0; o >>= 1)
        sum += __shfl_xor_sync(0xffffffffu, sum, o);
    __syncthreads();
    if ((tid & 31) == 0) red[tid >> 5] = sum;
    __syncthreads();
    {
        float s = red[tid & 7];
#pragma unroll
        for (int o = 4; o > 0; o >>= 1)
            s += __shfl_xor_sync(0xffffffffu, s, o);
        sum = s;
    }
    float inv = 1.0f / sum;

    v0.x *= inv; v0.y *= inv; v0.z *= inv; v0.w *= inv;
    v1.x *= inv; v1.y *= inv; v1.z *= inv; v1.w *= inv;
    reinterpret_cast<float4*>(p)[tid]       = v0;
    reinterpret_cast<float4*>(p)[tid + 256] = v1;
}

// ============================================================
// column sums (two stage)
// ============================================================
__global__ void colsum1_kernel(const float* __restrict__ probs)
{
    const int k  = blockIdx.x * 256 + threadIdx.x;
    const int b  = blockIdx.y;
    const int qc = blockIdx.z;
    const float* p = probs + (size_t)b * SEQ * SEQ + (size_t)qc * 128 * SEQ + k;
    float s = 0.f;
#pragma unroll 4
    for (int q = 0; q < 128; q++) s += p[(size_t)q * SEQ];
    g_cs_part[(size_t)(qc * BATCH + b) * SEQ + k] = s;
}

__global__ void colsum2_kernel()
{
    const int i = blockIdx.x * 256 + threadIdx.x;
    float s = 0.f;
#pragma unroll
    for (int c = 0; c < QCHUNK; c++) s += g_cs_part[(size_t)c * BATCH * SEQ + i];
    g_colsum[i] = s;
}

// ============================================================
// renorm in place + emit bf16 split A2 = [hi | lo]
// ============================================================
__global__ void renorm_split_kernel(float* __restrict__ probs)
{
    size_t i4 = ((size_t)blockIdx.x * 256 + threadIdx.x) * 4;
    int k = (int)(i4 & (SEQ - 1));
    int q = (int)((i4 >> 11) & (SEQ - 1));
    int b = (int)(i4 >> 22);
    float4 p = *reinterpret_cast<float4*>(&probs[i4]);
    const float4 c = *reinterpret_cast<const float4*>(&g_colsum[b * SEQ + k]);
    p.x /= (1e-9f + c.x);
    p.y /= (1e-9f + c.y);
    p.z /= (1e-9f + c.z);
    p.w /= (1e-9f + c.w);
    *reinterpret_cast<float4*>(&probs[i4]) = p;

    __nv_bfloat16 h0, h1, h2, h3, l0, l1, l2, l3;
    split2(p.x, h0, l0); split2(p.y, h1, l1);
    split2(p.z, h2, l2); split2(p.w, h3, l3);

    __nv_bfloat16* row = g_a2 + ((size_t)(b * SEQ + q)) * KP2;
    __nv_bfloat162 ha; ha.x = h0; ha.y = h1;
    __nv_bfloat162 hb; hb.x = h2; hb.y = h3;
    __nv_bfloat162 la; la.x = l0; la.y = l1;
    __nv_bfloat162 lb; lb.x = l2; lb.y = l3;
    *reinterpret_cast<__nv_bfloat162*>(row + k)           = ha;
    *reinterpret_cast<__nv_bfloat162*>(row + k + 2)       = hb;
    *reinterpret_cast<__nv_bfloat162*>(row + SEQ + k)     = la;
    *reinterpret_cast<__nv_bfloat162*>(row + SEQ + k + 2) = lb;
}

// ============================================================
// aten: out = probs @ v   (per batch 2048x1024, K=2048 split)
// ============================================================
__global__ void __launch_bounds__(256, 2) aten_mma_kernel(float* __restrict__ out)
{
    extern __shared__ char smem[];
    const int tid = threadIdx.x;
    const int wid = tid >> 5, lane = tid & 31;
    const int wm = wid & 3, wn = wid >> 2;
    const int b  = blockIdx.z;
    const int m0 = blockIdx.y * 128;
    const int n0 = blockIdx.x * 128;
    const uint32_t sbase = smem_u32(smem);

    GemmAcc g = {};
    gemm_split_mainloop(g, sbase,
                        g_a2 + (size_t)b * SEQ * KP2 + (size_t)m0 * KP2,
                        g_b2 + (size_t)b * DMODEL * KP2 + (size_t)n0 * KP2,
                        SEQ, KP2, SEQ / 64, tid, wm, wn, lane);

#pragma unroll
    for (int i = 0; i < 2; i++) {
        int q = m0 + wm * 32 + i * 16 + (lane >> 2);
#pragma unroll
        for (int j = 0; j < 8; j++) {
            int n = n0 + wn * 64 + j * 8 + (lane & 3) * 2;
            float2 lo = make_float2(g.a[i][j][0], g.a[i][j][1]);
            float2 hi = make_float2(g.a[i][j][2], g.a[i][j][3]);
            *reinterpret_cast<float2*>(out + ((size_t)q * BATCH + b) * DMODEL + n)       = lo;
            *reinterpret_cast<float2*>(out + ((size_t)(q + 8) * BATCH + b) * DMODEL + n) = hi;
        }
    }
}

// ============================================================
// stream/event setup at program init
// ============================================================
struct StreamInit {
    cudaStream_t s1 = nullptr, s2 = nullptr;
    cudaEvent_t  e0 = nullptr, e1 = nullptr, e2 = nullptr;
    StreamInit() {
        cudaStreamCreateWithFlags(&s1, cudaStreamNonBlocking);
        cudaStreamCreateWithFlags(&s2, cudaStreamNonBlocking);
        cudaEventCreateWithFlags(&e0, cudaEventDisableTiming);
        cudaEventCreateWithFlags(&e1, cudaEventDisableTiming);
        cudaEventCreateWithFlags(&e2, cudaEventDisableTiming);
        cudaFuncSetAttribute(aten_mma_kernel,   cudaFuncAttributeMaxDynamicSharedMemorySize, GM_SMEM);
        cudaFuncSetAttribute(projv_mma_kernel,  cudaFuncAttributeMaxDynamicSharedMemorySize, GM_SMEM);
        cudaFuncSetAttribute(scores_mma_kernel, cudaFuncAttributeMaxDynamicSharedMemorySize, GM_SMEM);
        noop_kernel<<<1, 32>>>();
        noop_kernel<<<1, 32, 0, s1>>>();
        noop_kernel<<<1, 32, 0, s2>>>();
        cudaDeviceSynchronize();
    }
};
static StreamInit g_si;

// ============================================================
extern "C" void kernel_launch(void* const* d_in, const int* in_sizes, int n_in,
                              void* d_out, int out_size)
{
    const float* query = (const float*)d_in[0];
    const float* key   = (const float*)d_in[1];
    const float* value = (const float*)d_in[2];
    const float* Wq    = (const float*)d_in[3];
    const float* bq    = (const float*)d_in[4];
    const float* Wk    = (const float*)d_in[5];
    const float* bk    = (const float*)d_in[6];
    const float* Wv    = (const float*)d_in[7];
    const float* bv    = (const float*)d_in[8];

    float* out   = (float*)d_out;
    float* aten  = out;                                   // (S, B, D)
    float* probs = out + (size_t)SEQ * BATCH * DMODEL;    // (B, S, S)

    cudaStream_t s1 = g_si.s1, s2 = g_si.s2;

    // ---- fork ----
    cudaEventRecord(g_si.e0, 0);
    cudaStreamWaitEvent(s1, g_si.e0, 0);
    cudaStreamWaitEvent(s2, g_si.e0, 0);

    // ===== chain A (s1): q/k split-K -> emit -> scores -> softmax -> colsum -> renorm =====
    {
        dim3 grid(MTOT / 64, PKC, 2);
        projqk_partial_kernel<<<grid, 256, 0, s1>>>(query, key, Wq, Wk);
    }
    qkemit_kernel<<<(2 * MTOT * 16) / 256, 256, 0, s1>>>(bq, bk);
    {
        dim3 grid(SEQ / 128, SEQ / 128, BATCH);
        scores_mma_kernel<<<grid, 256, GM_SMEM, s1>>>(probs);
    }
    rowsoftmax_kernel<<<BATCH * SEQ, 256, 0, s1>>>(probs);
    {
        dim3 grid(SEQ / 256, BATCH, QCHUNK);
        colsum1_kernel<<<grid, 256, 0, s1>>>(probs);
    }
    colsum2_kernel<<<BATCH * SEQ / 256, 256, 0, s1>>>();
    {
        size_t total4 = (size_t)BATCH * SEQ * SEQ / 4;
        renorm_split_kernel<<<(unsigned)(total4 / 256), 256, 0, s1>>>(probs);
    }

    // ===== chain B (s2): value split -> Wv split -> projv -> vsplit =====
    xvsplit_kernel<<<(MTOT * DMODEL / 4) / 256, 256, 0, s2>>>(value);
    {
        dim3 grid(DMODEL / 32, DMODEL / 32);
        wvsplit_kernel<<<grid, 256, 0, s2>>>(Wv);
    }
    {
        dim3 grid(DMODEL / 128, MTOT / 128);
        projv_mma_kernel<<<grid, 256, GM_SMEM, s2>>>(bv);
    }
    {
        dim3 grid(DMODEL / 32, SEQ / 32, BATCH);
        vsplit_kernel<<<grid, 256, 0, s2>>>();
    }

    // ---- join ----
    cudaEventRecord(g_si.e1, s1);
    cudaEventRecord(g_si.e2, s2);
    cudaStreamWaitEvent(0, g_si.e1, 0);
    cudaStreamWaitEvent(0, g_si.e2, 0);

    // aten = probs @ v  via split mma GEMM (stream 0)
    {
        dim3 grid(DMODEL / 128, SEQ / 128, BATCH);
        aten_mma_kernel<<<grid, 256, GM_SMEM>>>(aten);
    }
}